// round 9
// baseline (speedup 1.0000x reference)
#include <cuda_runtime.h>
#include <cuda_bf16.h>
#include <math.h>
#include <stdint.h>

#define N_TOK 2309
#define N_T   2304
#define CDIM  1024
#define HEADS 16
#define DH    64
#define REG_N 5
#define SCALE 0.125f   // 64^-0.5
#define NTILE 37
#define KEYPAD (NTILE * 64)   // 2368
#define NQT   73              // ceil(2309/32) query tiles of 32 rows

// ---------------- device scratch (static, no runtime alloc) ----------------
__device__ float g_qkv[(size_t)N_TOK * 3 * CDIM];
__device__ float g_attn[(size_t)N_TOK * CDIM];
__device__ float g_sim[N_T];
__device__ int   g_perm[N_TOK];
__device__ int   g_npos[1];
__device__ unsigned char g_flag[N_T];
// pre-converted bf16 hi/lo, permuted keys, fragment-ready layout
__device__ uint32_t g_kc [HEADS][KEYPAD][64];   // [head][key][slot]
__device__ uint32_t g_vtc[HEADS][DH][KEYPAD];   // [head][dim][tile*64+slot]

// ================= warp-level tf32 MMA GEMM (3xTF32) =========================
#define GPITCH 136
#define SLAB   32
#define OFF_AH 0
#define OFF_AL (SLAB * GPITCH)
#define OFF_BH (2 * SLAB * GPITCH)
#define OFF_BL (3 * SLAB * GPITCH)
#define GEMM_SMEM_FLOATS (4 * SLAB * GPITCH)

__device__ __forceinline__ float tf32r(float v)
{
    uint32_t u;
    asm("cvt.rna.tf32.f32 %0, %1;" : "=r"(u) : "f"(v));
    return __uint_as_float(u);
}

__device__ __forceinline__ void mma_tf32(float* d, const uint32_t* a, const uint32_t* b)
{
    asm volatile(
        "mma.sync.aligned.m16n8k8.row.col.f32.tf32.tf32.f32 "
        "{%0,%1,%2,%3}, {%4,%5,%6,%7}, {%8,%9}, {%0,%1,%2,%3};"
        : "+f"(d[0]), "+f"(d[1]), "+f"(d[2]), "+f"(d[3])
        : "r"(a[0]), "r"(a[1]), "r"(a[2]), "r"(a[3]), "r"(b[0]), "r"(b[1]));
}

__global__ __launch_bounds__(256) void gemm_mma(
    const float* __restrict__ A, const float* __restrict__ B,
    const float* __restrict__ bias, float* __restrict__ C,
    int M, int N, int K)
{
    extern __shared__ float sm[];
    float* sAh = sm + OFF_AH;
    float* sAl = sm + OFF_AL;
    float* sBh = sm + OFF_BH;
    float* sBl = sm + OFF_BL;

    int tid = threadIdx.x;
    int warp = tid >> 5, lane = tid & 31;
    int g = lane >> 2, t = lane & 3;
    int mw = (warp >> 1) * 32;
    int nw = (warp & 1) * 64;
    int brow = blockIdx.y, bcol = blockIdx.x;

    int aRow = tid >> 1;
    int aHalf = (tid & 1) * 16;
    int aRowG = brow * 128 + aRow;
    bool aok = aRowG < M;
    const float* aptr = A + (size_t)aRowG * K + aHalf;
    int bK = tid >> 3;
    int bN0 = (tid & 7) * 16;
    const float* bptr = B + (size_t)bK * N + bcol * 128 + bN0;

    float c[64];
#pragma unroll
    for (int i = 0; i < 64; i++) c[i] = 0.f;

    int nslab = K / SLAB;
    for (int s = 0; s < nslab; s++) {
        if (s) __syncthreads();
#pragma unroll
        for (int j = 0; j < 4; j++) {
            float4 v = make_float4(0.f, 0.f, 0.f, 0.f);
            if (aok) v = *(const float4*)(aptr + s * SLAB + j * 4);
            int k0 = aHalf + j * 4;
            float hx = tf32r(v.x), hy = tf32r(v.y), hz = tf32r(v.z), hw = tf32r(v.w);
            sAh[(k0 + 0) * GPITCH + aRow] = hx;
            sAh[(k0 + 1) * GPITCH + aRow] = hy;
            sAh[(k0 + 2) * GPITCH + aRow] = hz;
            sAh[(k0 + 3) * GPITCH + aRow] = hw;
            sAl[(k0 + 0) * GPITCH + aRow] = tf32r(v.x - hx);
            sAl[(k0 + 1) * GPITCH + aRow] = tf32r(v.y - hy);
            sAl[(k0 + 2) * GPITCH + aRow] = tf32r(v.z - hz);
            sAl[(k0 + 3) * GPITCH + aRow] = tf32r(v.w - hw);
        }
#pragma unroll
        for (int j = 0; j < 4; j++) {
            float4 v = *(const float4*)(bptr + (size_t)s * SLAB * N + j * 4);
            float4 hi, lo;
            hi.x = tf32r(v.x); lo.x = tf32r(v.x - hi.x);
            hi.y = tf32r(v.y); lo.y = tf32r(v.y - hi.y);
            hi.z = tf32r(v.z); lo.z = tf32r(v.z - hi.z);
            hi.w = tf32r(v.w); lo.w = tf32r(v.w - hi.w);
            *(float4*)&sBh[bK * GPITCH + bN0 + j * 4] = hi;
            *(float4*)&sBl[bK * GPITCH + bN0 + j * 4] = lo;
        }
        __syncthreads();
#pragma unroll
        for (int kk = 0; kk < SLAB; kk += 8) {
            uint32_t ah[2][4], al[2][4];
#pragma unroll
            for (int am = 0; am < 2; am++) {
                int m0 = mw + am * 16 + g;
#pragma unroll
                for (int rr = 0; rr < 4; rr++) {
                    int k = kk + t + ((rr >> 1) << 2);
                    int m = m0 + ((rr & 1) << 3);
                    ah[am][rr] = __float_as_uint(sAh[k * GPITCH + m]);
                    al[am][rr] = __float_as_uint(sAl[k * GPITCH + m]);
                }
            }
#pragma unroll
            for (int an = 0; an < 8; an++) {
                int n = nw + an * 8 + g;
                uint32_t bh[2], bl[2];
#pragma unroll
                for (int rr = 0; rr < 2; rr++) {
                    int k = kk + t + rr * 4;
                    bh[rr] = __float_as_uint(sBh[k * GPITCH + n]);
                    bl[rr] = __float_as_uint(sBl[k * GPITCH + n]);
                }
#pragma unroll
                for (int am = 0; am < 2; am++) {
                    float* cc = &c[(am * 8 + an) * 4];
                    mma_tf32(cc, ah[am], bh);
                    mma_tf32(cc, al[am], bh);
                    mma_tf32(cc, ah[am], bl);
                }
            }
        }
    }

#pragma unroll
    for (int am = 0; am < 2; am++) {
#pragma unroll
        for (int an = 0; an < 8; an++) {
            float* cc = &c[(am * 8 + an) * 4];
            int row0 = brow * 128 + mw + am * 16 + g;
            int col = bcol * 128 + nw + an * 8 + 2 * t;
            float bx = 0.f, by = 0.f;
            if (bias) { bx = bias[col]; by = bias[col + 1]; }
            if (row0 < M) {
                float2 o; o.x = cc[0] + bx; o.y = cc[1] + by;
                *(float2*)(C + (size_t)row0 * N + col) = o;
            }
            if (row0 + 8 < M) {
                float2 o; o.x = cc[2] + bx; o.y = cc[3] + by;
                *(float2*)(C + (size_t)(row0 + 8) * N + col) = o;
            }
        }
    }
}

// ---------------- similarity ----------------
__global__ void sim_kernel(const float* __restrict__ g_info)
{
    int t = blockIdx.x;
    int lane = threadIdx.x & 31, warp = threadIdx.x >> 5;
    __shared__ float wacc[4];
    const float* qrow = g_qkv + (size_t)(t + REG_N) * (3 * CDIM);
    float local = 0.f;
    for (int h = warp; h < HEADS; h += 4) {
        float q0 = qrow[h * DH + lane];
        float q1 = qrow[h * DH + lane + 32];
        float g0 = g_info[h * DH + lane];
        float g1 = g_info[h * DH + lane + 32];
        float d = q0 * g0 + q1 * g1;
        float nq = q0 * q0 + q1 * q1;
        float ng = g0 * g0 + g1 * g1;
#pragma unroll
        for (int o = 16; o > 0; o >>= 1) {
            d  += __shfl_xor_sync(0xffffffffu, d, o);
            nq += __shfl_xor_sync(0xffffffffu, nq, o);
            ng += __shfl_xor_sync(0xffffffffu, ng, o);
        }
        if (lane == 0) local += d / (sqrtf(nq) * sqrtf(ng));
    }
    if (lane == 0) wacc[warp] = local;
    __syncthreads();
    if (threadIdx.x == 0)
        g_sim[t] = (wacc[0] + wacc[1] + wacc[2] + wacc[3]) * (1.0f / 16.0f);
}

// ---------------- minmax + threshold + scan -> key permutation --------------
__global__ void maskscan_kernel()
{
    int tid = threadIdx.x;
    int lane = tid & 31, warp = tid >> 5;
    int t0 = tid * 3;
    float v0 = g_sim[t0], v1 = g_sim[t0 + 1], v2 = g_sim[t0 + 2];
    float mn = fminf(v0, fminf(v1, v2));
    float mx = fmaxf(v0, fmaxf(v1, v2));
#pragma unroll
    for (int o = 16; o > 0; o >>= 1) {
        mn = fminf(mn, __shfl_xor_sync(0xffffffffu, mn, o));
        mx = fmaxf(mx, __shfl_xor_sync(0xffffffffu, mx, o));
    }
    __shared__ float smn[24], smx[24];
    __shared__ float s_bmn, s_bmx;
    if (lane == 0) { smn[warp] = mn; smx[warp] = mx; }
    __syncthreads();
    if (tid == 0) {
        float a = smn[0], b = smx[0];
        for (int w = 1; w < 24; w++) { a = fminf(a, smn[w]); b = fmaxf(b, smx[w]); }
        s_bmn = a; s_bmx = b;
    }
    __syncthreads();
    float bmn = s_bmn;
    float inv = 1.0f / (s_bmx - bmn);
    int f[3]; int c = 0;
    f[0] = ((v0 - bmn) * inv > 0.9f) ? 1 : 0;
    f[1] = ((v1 - bmn) * inv > 0.9f) ? 1 : 0;
    f[2] = ((v2 - bmn) * inv > 0.9f) ? 1 : 0;
#pragma unroll
    for (int e = 0; e < 3; e++) {
        c += f[e];
        g_flag[t0 + e] = (unsigned char)f[e];
    }
    int incl = c;
#pragma unroll
    for (int o = 1; o < 32; o <<= 1) {
        int v = __shfl_up_sync(0xffffffffu, incl, o);
        if (lane >= o) incl += v;
    }
    __shared__ int wsum[24];
    __shared__ int s_npos;
    if (lane == 31) wsum[warp] = incl;
    __syncthreads();
    if (tid == 0) {
        int acc = 0;
        for (int w = 0; w < 24; w++) { int v = wsum[w]; wsum[w] = acc; acc += v; }
        s_npos = acc;
        g_npos[0] = acc;
        for (int i = 0; i < REG_N; i++) g_perm[i] = i;
    }
    __syncthreads();
    int excl = incl - c + wsum[warp];
    int npos = s_npos;
    int pp = excl;
#pragma unroll
    for (int e = 0; e < 3; e++) {
        int t = t0 + e;
        if (f[e]) { g_perm[REG_N + pp] = t + REG_N; pp++; }
        else      { g_perm[REG_N + npos + (t - pp)] = t + REG_N; }
    }
}

// ================== helpers ==================
__device__ __forceinline__ float bf16rt(float x)
{
    __nv_bfloat16 h = __float2bfloat16(x);
    return __bfloat162float(h);
}
__device__ __forceinline__ uint32_t pack2(float lo, float hi)
{
    uint32_t r;
    asm("cvt.rn.bf16x2.f32 %0, %1, %2;" : "=r"(r) : "f"(hi), "f"(lo));
    return r;
}
__device__ __forceinline__ void mma16816(float* d, const uint32_t* a, const uint32_t* b)
{
    asm volatile(
        "mma.sync.aligned.m16n8k16.row.col.f32.bf16.bf16.f32 "
        "{%0,%1,%2,%3},{%4,%5,%6,%7},{%8,%9},{%0,%1,%2,%3};"
        : "+f"(d[0]), "+f"(d[1]), "+f"(d[2]), "+f"(d[3])
        : "r"(a[0]), "r"(a[1]), "r"(a[2]), "r"(a[3]), "r"(b[0]), "r"(b[1]));
}
__device__ __forceinline__ uint32_t smem_u32(const void* p)
{
    uint32_t a;
    asm("{ .reg .u64 t; cvta.to.shared.u64 t, %1; cvt.u32.u64 %0, t; }" : "=r"(a) : "l"(p));
    return a;
}

// ============ pre-convert: permuted K / V^T -> bf16 hi/lo fragment layout ====
__global__ __launch_bounds__(256) void preconv_kernel(int /*dummy*/)
{
    __shared__ __nv_bfloat16 sVH[64][66];
    __shared__ __nv_bfloat16 sVL[64][66];
    int tile = blockIdx.x, h = blockIdx.y;
    int tid = threadIdx.x;
    int keyl = tid >> 2, grp = tid & 3;
    int kidx = tile * 64 + keyl;
    bool ok = kidx < N_TOK;
    int src = ok ? g_perm[kidx] : 0;
    const float* kr = g_qkv + (size_t)src * (3 * CDIM) + CDIM + h * DH + grp * 16;
    const float* vr = kr + CDIM;

    float kb[16], vb[16];
#pragma unroll
    for (int j = 0; j < 4; j++) {
        float4 kv = ok ? *(const float4*)(kr + j * 4) : make_float4(0.f, 0.f, 0.f, 0.f);
        float4 vv = ok ? *(const float4*)(vr + j * 4) : make_float4(0.f, 0.f, 0.f, 0.f);
        kb[j * 4 + 0] = kv.x; kb[j * 4 + 1] = kv.y; kb[j * 4 + 2] = kv.z; kb[j * 4 + 3] = kv.w;
        vb[j * 4 + 0] = vv.x; vb[j * 4 + 1] = vv.y; vb[j * 4 + 2] = vv.z; vb[j * 4 + 3] = vv.w;
    }
    uint32_t* kout = &g_kc[h][kidx][grp * 16];
#pragma unroll
    for (int pj = 0; pj < 8; pj++) {
        float a = kb[2 * pj], b = kb[2 * pj + 1];
        float ha = bf16rt(a), hb = bf16rt(b);
        int sh = 4 * (pj & 3) + (pj >> 2);
        kout[sh] = pack2(ha, hb);
        kout[sh + 2] = pack2(a - ha, b - hb);
    }
#pragma unroll
    for (int d = 0; d < 16; d++) {
        float v = vb[d];
        float hv = bf16rt(v);
        sVH[grp * 16 + d][keyl] = __float2bfloat16(v);
        sVL[grp * 16 + d][keyl] = __float2bfloat16(v - hv);
    }
    __syncthreads();
    int dim = tid >> 2, grp2 = tid & 3;
    uint32_t* vout = &g_vtc[h][dim][tile * 64 + grp2 * 16];
#pragma unroll
    for (int pj = 0; pj < 8; pj++) {
        int k0 = grp2 * 16 + 2 * pj;
        uint32_t hi = ((uint32_t)__bfloat16_as_ushort(sVH[dim][k0 + 1]) << 16)
                    | __bfloat16_as_ushort(sVH[dim][k0]);
        uint32_t lo = ((uint32_t)__bfloat16_as_ushort(sVL[dim][k0 + 1]) << 16)
                    | __bfloat16_as_ushort(sVL[dim][k0]);
        int sh = 4 * (pj & 3) + (pj >> 2);
        vout[sh] = hi;
        vout[sh + 2] = lo;
    }
}

// ================== tensor-core flash attention (bf16x3, cp.async) ===========
// 128-thread CTA, 32 query rows: warps = 2 mi x 2 hf; 3 CTAs/SM target.
#define FS_STAGE_U32 8704           // K 64*68 + VT 64*68
#define FS_STAGE_BYTES (FS_STAGE_U32 * 4)
#define FS_RED_U32 (2 * FS_STAGE_U32)
#define FS_TOTAL_BYTES ((FS_RED_U32 + 224) * 4)

__device__ __forceinline__ void copy_tile(uint32_t dstb, int ti, int h, int tid)
{
    int row = tid >> 1, s2 = (tid & 1) * 2;   // two 16-u32 segments per thread
    uint32_t kd = dstb + (uint32_t)(row * 68 + s2 * 16) * 4;
    const uint32_t* ksp = &g_kc[h][ti * 64 + row][s2 * 16];
    uint32_t vd = dstb + (uint32_t)(4352 + row * 68 + s2 * 16) * 4;
    const uint32_t* vsp = &g_vtc[h][row][ti * 64 + s2 * 16];
#pragma unroll
    for (int c = 0; c < 8; c++) {
        asm volatile("cp.async.ca.shared.global [%0], [%1], 16;"
                     :: "r"(kd + c * 16), "l"(ksp + c * 4) : "memory");
        asm volatile("cp.async.ca.shared.global [%0], [%1], 16;"
                     :: "r"(vd + c * 16), "l"(vsp + c * 4) : "memory");
    }
}

#define PAIR_BAR(mi) asm volatile("bar.sync %0, 64;" :: "r"((mi) + 1) : "memory")

template <int GRP>
__device__ __forceinline__ void group_pass(
    float sacc[4][4], float o[8][4], const uint32_t* Vb,
    float* red0, float* red1, float* s_m, float* s_l, float* s_al,
    int base, int pend, int tid, int g, int t, int mi, int hf)
{
    int r0 = mi * 16 + g, r1 = r0 + 8;
    float pm0 = -1e30f, pm1 = -1e30f;
#pragma unroll
    for (int nj = 0; nj < 4; nj++) {
        int kc = base + (hf * 4 + nj) * 8 + 2 * t;
        bool in0 = (GRP == 0) ? (kc < pend)
                              : ((kc < REG_N) || (kc >= pend && kc < N_TOK));
        bool in1 = (GRP == 0) ? (kc + 1 < pend)
                              : ((kc + 1 < REG_N) || (kc + 1 >= pend && kc + 1 < N_TOK));
        if (in0) { pm0 = fmaxf(pm0, sacc[nj][0]); pm1 = fmaxf(pm1, sacc[nj][2]); }
        if (in1) { pm0 = fmaxf(pm0, sacc[nj][1]); pm1 = fmaxf(pm1, sacc[nj][3]); }
    }
    pm0 = fmaxf(pm0, __shfl_xor_sync(0xffffffffu, pm0, 1));
    pm0 = fmaxf(pm0, __shfl_xor_sync(0xffffffffu, pm0, 2));
    pm1 = fmaxf(pm1, __shfl_xor_sync(0xffffffffu, pm1, 1));
    pm1 = fmaxf(pm1, __shfl_xor_sync(0xffffffffu, pm1, 2));
    if (t == 0) {
        float* rd = hf ? red1 : red0;
        rd[r0] = pm0; rd[r1] = pm1;
    }
    PAIR_BAR(mi);
    if (hf == 0 && t == 0) {
#pragma unroll
        for (int rr = 0; rr < 2; rr++) {
            int r = rr ? r1 : r0;
            float mt = fmaxf(red0[r], red1[r]);
            float mo = s_m[r];
            float mn2 = fmaxf(mo, mt);
            s_al[r] = __expf(mo - mn2);
            s_m[r] = mn2;
        }
    }
    PAIR_BAR(mi);
    float m0 = s_m[r0], m1 = s_m[r1];
    float p[4][4];
    float ps0 = 0.f, ps1 = 0.f;
#pragma unroll
    for (int nj = 0; nj < 4; nj++) {
        int kc = base + (hf * 4 + nj) * 8 + 2 * t;
        bool in0 = (GRP == 0) ? (kc < pend)
                              : ((kc < REG_N) || (kc >= pend && kc < N_TOK));
        bool in1 = (GRP == 0) ? (kc + 1 < pend)
                              : ((kc + 1 < REG_N) || (kc + 1 >= pend && kc + 1 < N_TOK));
        p[nj][0] = in0 ? __expf(sacc[nj][0] - m0) : 0.f;
        p[nj][1] = in1 ? __expf(sacc[nj][1] - m0) : 0.f;
        p[nj][2] = in0 ? __expf(sacc[nj][2] - m1) : 0.f;
        p[nj][3] = in1 ? __expf(sacc[nj][3] - m1) : 0.f;
        ps0 += p[nj][0] + p[nj][1];
        ps1 += p[nj][2] + p[nj][3];
    }
    ps0 += __shfl_xor_sync(0xffffffffu, ps0, 1);
    ps0 += __shfl_xor_sync(0xffffffffu, ps0, 2);
    ps1 += __shfl_xor_sync(0xffffffffu, ps1, 1);
    ps1 += __shfl_xor_sync(0xffffffffu, ps1, 2);
    if (t == 0) {
        float* rd = hf ? red1 : red0;
        rd[r0] = ps0; rd[r1] = ps1;
    }
    PAIR_BAR(mi);
    if (hf == 0 && t == 0) {
        s_l[r0] = s_l[r0] * s_al[r0] + red0[r0] + red1[r0];
        s_l[r1] = s_l[r1] * s_al[r1] + red0[r1] + red1[r1];
    }
    PAIR_BAR(mi);
    float al0 = s_al[r0], al1 = s_al[r1];
#pragma unroll
    for (int nd = 0; nd < 8; nd++) {
        o[nd][0] *= al0; o[nd][1] *= al0;
        o[nd][2] *= al1; o[nd][3] *= al1;
    }
    uint32_t ah[2][4], alo[2][4];
#pragma unroll
    for (int ks = 0; ks < 2; ks++) {
        float h00 = bf16rt(p[2 * ks][0]),     h01 = bf16rt(p[2 * ks][1]);
        float h02 = bf16rt(p[2 * ks][2]),     h03 = bf16rt(p[2 * ks][3]);
        float h10 = bf16rt(p[2 * ks + 1][0]), h11 = bf16rt(p[2 * ks + 1][1]);
        float h12 = bf16rt(p[2 * ks + 1][2]), h13 = bf16rt(p[2 * ks + 1][3]);
        ah[ks][0] = pack2(h00, h01);
        ah[ks][1] = pack2(h02, h03);
        ah[ks][2] = pack2(h10, h11);
        ah[ks][3] = pack2(h12, h13);
        alo[ks][0] = pack2(p[2 * ks][0] - h00,     p[2 * ks][1] - h01);
        alo[ks][1] = pack2(p[2 * ks][2] - h02,     p[2 * ks][3] - h03);
        alo[ks][2] = pack2(p[2 * ks + 1][0] - h10, p[2 * ks + 1][1] - h11);
        alo[ks][3] = pack2(p[2 * ks + 1][2] - h12, p[2 * ks + 1][3] - h13);
    }
#pragma unroll
    for (int nd = 0; nd < 8; nd++) {
        int db = (nd * 8 + g) * 68;
#pragma unroll
        for (int ks = 0; ks < 2; ks++) {
            uint4 vv = *(const uint4*)&Vb[db + (2 * hf + ks) * 16 + 4 * t];
            uint32_t bh[2] = { vv.x, vv.y };
            uint32_t bl[2] = { vv.z, vv.w };
            mma16816(o[nd], ah[ks], bh);
            mma16816(o[nd], alo[ks], bh);
            mma16816(o[nd], ah[ks], bl);
        }
    }
}

__global__ void __launch_bounds__(128, 3) flash_kernel(int /*dummy*/)
{
    extern __shared__ char smc[];
    uint32_t* su = (uint32_t*)smc;
    float* fred = (float*)smc + FS_RED_U32;
    float* red0 = fred;          // [32]
    float* red1 = fred + 32;
    float* s_mp = fred + 64;
    float* s_lp = fred + 96;
    float* s_mn = fred + 128;
    float* s_ln = fred + 160;
    float* s_al = fred + 192;

    int tid = threadIdx.x;
    int warp = tid >> 5, lane = tid & 31;
    int g = lane >> 2, t = lane & 3;
    int mi = warp >> 1, hf = warp & 1;   // mi in {0,1}
    int h = blockIdx.y, qt = blockIdx.x;
    int qbase = qt * 32;
    int pend = REG_N + g_npos[0];
    uint32_t sbyte = smem_u32(smc);

    // Q fragments (hi/lo bf16), scaled
    uint32_t Qh[4][4], Ql[4][4];
    {
        int r0g = qbase + mi * 16 + g;
        int r1g = r0g + 8;
        bool ok0 = r0g < N_TOK, ok1 = r1g < N_TOK;
        const float* q0p = g_qkv + (size_t)r0g * (3 * CDIM) + h * DH;
        const float* q1p = g_qkv + (size_t)r1g * (3 * CDIM) + h * DH;
#pragma unroll
        for (int ks = 0; ks < 4; ks++) {
            int d0 = ks * 16 + 2 * t;
            float2 x0 = ok0 ? *(const float2*)(q0p + d0) : make_float2(0.f, 0.f);
            float2 x1 = ok1 ? *(const float2*)(q1p + d0) : make_float2(0.f, 0.f);
            float2 x2 = ok0 ? *(const float2*)(q0p + d0 + 8) : make_float2(0.f, 0.f);
            float2 x3 = ok1 ? *(const float2*)(q1p + d0 + 8) : make_float2(0.f, 0.f);
            x0.x *= SCALE; x0.y *= SCALE; x1.x *= SCALE; x1.y *= SCALE;
            x2.x *= SCALE; x2.y *= SCALE; x3.x *= SCALE; x3.y *= SCALE;
            float h0x = bf16rt(x0.x), h0y = bf16rt(x0.y);
            float h1x = bf16rt(x1.x), h1y = bf16rt(x1.y);
            float h2x = bf16rt(x2.x), h2y = bf16rt(x2.y);
            float h3x = bf16rt(x3.x), h3y = bf16rt(x3.y);
            Qh[ks][0] = pack2(h0x, h0y); Ql[ks][0] = pack2(x0.x - h0x, x0.y - h0y);
            Qh[ks][1] = pack2(h1x, h1y); Ql[ks][1] = pack2(x1.x - h1x, x1.y - h1y);
            Qh[ks][2] = pack2(h2x, h2y); Ql[ks][2] = pack2(x2.x - h2x, x2.y - h2y);
            Qh[ks][3] = pack2(h3x, h3y); Ql[ks][3] = pack2(x3.x - h3x, x3.y - h3y);
        }
    }
    if (tid < 32) {
        s_mp[tid] = -1e30f; s_lp[tid] = 0.f;
        s_mn[tid] = -1e30f; s_ln[tid] = 0.f;
    }
    float o[2][8][4];
#pragma unroll
    for (int gi = 0; gi < 2; gi++)
#pragma unroll
        for (int nd = 0; nd < 8; nd++)
#pragma unroll
            for (int e = 0; e < 4; e++) o[gi][nd][e] = 0.f;

    // preload tile 0
    copy_tile(sbyte, 0, h, tid);
    asm volatile("cp.async.commit_group;" ::: "memory");

    for (int ti = 0; ti < NTILE; ti++) {
        if (ti + 1 < NTILE) {
            copy_tile(sbyte + ((ti + 1) & 1) * FS_STAGE_BYTES, ti + 1, h, tid);
            asm volatile("cp.async.commit_group;" ::: "memory");
            asm volatile("cp.async.wait_group 1;" ::: "memory");
        } else {
            asm volatile("cp.async.wait_group 0;" ::: "memory");
        }
        __syncthreads();
        const uint32_t* Kb = su + (ti & 1) * FS_STAGE_U32;
        const uint32_t* Vb = Kb + 4352;
        int base = ti * 64;

        float sacc[4][4];
#pragma unroll
        for (int nj = 0; nj < 4; nj++)
#pragma unroll
            for (int e = 0; e < 4; e++) sacc[nj][e] = 0.f;
#pragma unroll
        for (int nj = 0; nj < 4; nj++) {
            int keyb = ((hf * 4 + nj) * 8 + g) * 68;
#pragma unroll
            for (int ks = 0; ks < 4; ks++) {
                uint4 kv = *(const uint4*)&Kb[keyb + ks * 16 + 4 * t];
                uint32_t bh[2] = { kv.x, kv.y };
                uint32_t bl[2] = { kv.z, kv.w };
                mma16816(sacc[nj], Qh[ks], bh);
                mma16816(sacc[nj], Ql[ks], bh);
                mma16816(sacc[nj], Qh[ks], bl);
            }
        }
        bool runPos = base < pend;
        bool runNeg = (base < REG_N) || (base + 64 > pend);
        if (runPos)
            group_pass<0>(sacc, o[0], Vb, red0, red1,
                          s_mp, s_lp, s_al, base, pend, tid, g, t, mi, hf);
        if (runNeg)
            group_pass<1>(sacc, o[1], Vb, red0, red1,
                          s_mn, s_ln, s_al, base, pend, tid, g, t, mi, hf);
        __syncthreads();
    }

    // ---- epilogue: combine warp halves, normalize, pos/neg select ----
    float* PB = (float*)smc;             // [32][72]
    float* NB = PB + 32 * 72;
    int r0 = mi * 16 + g, r1 = r0 + 8;
    if (hf == 1) {
#pragma unroll
        for (int nd = 0; nd < 8; nd++) {
            int c = nd * 8 + 2 * t;
            *(float2*)&PB[r0 * 72 + c] = make_float2(o[0][nd][0], o[0][nd][1]);
            *(float2*)&PB[r1 * 72 + c] = make_float2(o[0][nd][2], o[0][nd][3]);
            *(float2*)&NB[r0 * 72 + c] = make_float2(o[1][nd][0], o[1][nd][1]);
            *(float2*)&NB[r1 * 72 + c] = make_float2(o[1][nd][2], o[1][nd][3]);
        }
    }
    __syncthreads();
    if (hf == 0) {
        int q0 = qbase + r0, q1 = qbase + r1;
        float invlp0 = 1.f / s_lp[r0], invlp1 = 1.f / s_lp[r1];
        float invln0 = 1.f / s_ln[r0], invln1 = 1.f / s_ln[r1];
        bool reg0 = q0 < REG_N, reg1 = q1 < REG_N;
        float fl0 = (q0 >= REG_N && q0 < N_TOK) ? (g_flag[q0 - REG_N] ? 1.f : 0.f) : 0.f;
        float fl1 = (q1 >= REG_N && q1 < N_TOK) ? (g_flag[q1 - REG_N] ? 1.f : 0.f) : 0.f;
#pragma unroll
        for (int nd = 0; nd < 8; nd++) {
            int c = nd * 8 + 2 * t;
            float2 pp0 = *(float2*)&PB[r0 * 72 + c];
            float2 pp1 = *(float2*)&PB[r1 * 72 + c];
            float2 nn0 = *(float2*)&NB[r0 * 72 + c];
            float2 nn1 = *(float2*)&NB[r1 * 72 + c];
            float opx = (o[0][nd][0] + pp0.x) * invlp0;
            float opy = (o[0][nd][1] + pp0.y) * invlp0;
            float onx = (o[1][nd][0] + nn0.x) * invln0;
            float ony = (o[1][nd][1] + nn0.y) * invln0;
            float vx, vy;
            if (reg0) { vx = 0.5f * (opx + onx); vy = 0.5f * (opy + ony); }
            else      { vx = fl0 ? opx : onx;    vy = fl0 ? opy : ony; }
            if (q0 < N_TOK)
                *(float2*)(g_attn + (size_t)q0 * CDIM + h * DH + c) = make_float2(vx, vy);
            float opx1 = (o[0][nd][2] + pp1.x) * invlp1;
            float opy1 = (o[0][nd][3] + pp1.y) * invlp1;
            float onx1 = (o[1][nd][2] + nn1.x) * invln1;
            float ony1 = (o[1][nd][3] + nn1.y) * invln1;
            float wx, wy;
            if (reg1) { wx = 0.5f * (opx1 + onx1); wy = 0.5f * (opy1 + ony1); }
            else      { wx = fl1 ? opx1 : onx1;    wy = fl1 ? opy1 : ony1; }
            if (q1 < N_TOK)
                *(float2*)(g_attn + (size_t)q1 * CDIM + h * DH + c) = make_float2(wx, wy);
        }
    }
}

// ---------------- launcher ----------------
extern "C" void kernel_launch(void* const* d_in, const int* in_sizes, int n_in,
                              void* d_out, int out_size)
{
    const float* x = nullptr; const float* ginfo = nullptr;
    const float* wqkv = nullptr; const float* wproj = nullptr;
    const float* bproj = nullptr;
    for (int i = 0; i < n_in; i++) {
        switch (in_sizes[i]) {
            case N_TOK * CDIM:      x = (const float*)d_in[i]; break;
            case 12 * 2 * CDIM:     ginfo = (const float*)d_in[i]; break;
            case CDIM * 3 * CDIM:   wqkv = (const float*)d_in[i]; break;
            case CDIM * CDIM:       wproj = (const float*)d_in[i]; break;
            case CDIM:              bproj = (const float*)d_in[i]; break;
        }
    }
    float* out = (float*)d_out;

    float* qkv;  cudaGetSymbolAddress((void**)&qkv,  g_qkv);
    float* attn; cudaGetSymbolAddress((void**)&attn, g_attn);

    int gsmem = GEMM_SMEM_FLOATS * (int)sizeof(float);
    cudaFuncSetAttribute(gemm_mma, cudaFuncAttributeMaxDynamicSharedMemorySize, gsmem);
    cudaFuncSetAttribute(flash_kernel, cudaFuncAttributeMaxDynamicSharedMemorySize,
                         FS_TOTAL_BYTES);

    // [1] QKV GEMM (tf32 mma x3)
    gemm_mma<<<dim3(3 * CDIM / 128, (N_TOK + 127) / 128), 256, gsmem>>>(
        x, wqkv, nullptr, qkv, N_TOK, 3 * CDIM, CDIM);
    // [2] similarity
    sim_kernel<<<N_T, 128>>>(ginfo);
    // [3] minmax + mask + scan
    maskscan_kernel<<<1, 768>>>();
    // [4] pre-convert permuted K / V^T to bf16 hi/lo fragment layout
    preconv_kernel<<<dim3(NTILE, HEADS), 256>>>(0);
    // [5] flash attention (128-thread CTAs, 3/SM)
    flash_kernel<<<dim3(NQT, HEADS), 128, FS_TOTAL_BYTES>>>(0);
    // [6] projection GEMM + bias
    gemm_mma<<<dim3(CDIM / 128, (N_TOK + 127) / 128), 256, gsmem>>>(
        attn, wproj, bproj, out, N_TOK, CDIM, CDIM);
}

// round 10
// speedup vs baseline: 1.3790x; 1.3790x over previous
#include <cuda_runtime.h>
#include <cuda_bf16.h>
#include <math.h>
#include <stdint.h>

#define N_TOK 2309
#define N_T   2304
#define CDIM  1024
#define HEADS 16
#define DH    64
#define REG_N 5
#define SCALE 0.125f   // 64^-0.5
#define NTILE 37
#define KEYPAD (NTILE * 64)   // 2368

// ---------------- device scratch (static, no runtime alloc) ----------------
__device__ float g_qkv[(size_t)N_TOK * 3 * CDIM];
__device__ float g_attn[(size_t)N_TOK * CDIM];
__device__ float g_sim[N_T];
__device__ int   g_perm[N_TOK];
__device__ int   g_npos[1];
__device__ unsigned char g_flag[N_T];
// pre-converted bf16 hi/lo, permuted keys, fragment-ready layout
__device__ uint32_t g_kc [HEADS][KEYPAD][64];   // [head][key][slot]
__device__ uint32_t g_vtc[HEADS][DH][KEYPAD];   // [head][dim][tile*64+slot]

// ================= warp-level tf32 MMA GEMM (3xTF32, reg-pipelined) ==========
#define GPITCH 136
#define SLAB   32
#define OFF_AH 0
#define OFF_AL (SLAB * GPITCH)
#define OFF_BH (2 * SLAB * GPITCH)
#define OFF_BL (3 * SLAB * GPITCH)
#define GEMM_SMEM_FLOATS (4 * SLAB * GPITCH)

__device__ __forceinline__ float tf32r(float v)
{
    uint32_t u;
    asm("cvt.rna.tf32.f32 %0, %1;" : "=r"(u) : "f"(v));
    return __uint_as_float(u);
}

__device__ __forceinline__ void mma_tf32(float* d, const uint32_t* a, const uint32_t* b)
{
    asm volatile(
        "mma.sync.aligned.m16n8k8.row.col.f32.tf32.tf32.f32 "
        "{%0,%1,%2,%3}, {%4,%5,%6,%7}, {%8,%9}, {%0,%1,%2,%3};"
        : "+f"(d[0]), "+f"(d[1]), "+f"(d[2]), "+f"(d[3])
        : "r"(a[0]), "r"(a[1]), "r"(a[2]), "r"(a[3]), "r"(b[0]), "r"(b[1]));
}

__global__ __launch_bounds__(256) void gemm_mma(
    const float* __restrict__ A, const float* __restrict__ B,
    const float* __restrict__ bias, float* __restrict__ C,
    int M, int N, int K)
{
    extern __shared__ float sm[];
    float* sAh = sm + OFF_AH;
    float* sAl = sm + OFF_AL;
    float* sBh = sm + OFF_BH;
    float* sBl = sm + OFF_BL;

    int tid = threadIdx.x;
    int warp = tid >> 5, lane = tid & 31;
    int g = lane >> 2, t = lane & 3;
    int mw = (warp >> 1) * 32;
    int nw = (warp & 1) * 64;
    int brow = blockIdx.y, bcol = blockIdx.x;

    int aRow = tid >> 1;
    int aHalf = (tid & 1) * 16;
    int aRowG = brow * 128 + aRow;
    bool aok = aRowG < M;
    const float* aptr = A + (size_t)aRowG * K + aHalf;
    int bK = tid >> 3;
    int bN0 = (tid & 7) * 16;
    const float* bptr = B + (size_t)bK * N + bcol * 128 + bN0;

    float c[64];
#pragma unroll
    for (int i = 0; i < 64; i++) c[i] = 0.f;

    int nslab = K / SLAB;
    float4 avr[4], bvr[4];
    // prologue: load slab 0 into registers
#pragma unroll
    for (int j = 0; j < 4; j++) {
        avr[j] = aok ? *(const float4*)(aptr + j * 4)
                     : make_float4(0.f, 0.f, 0.f, 0.f);
        bvr[j] = *(const float4*)(bptr + j * 4);
    }

    for (int s = 0; s < nslab; s++) {
        // ---- convert + store current regs to smem ----
#pragma unroll
        for (int j = 0; j < 4; j++) {
            float4 v = avr[j];
            int k0 = aHalf + j * 4;
            float hx = tf32r(v.x), hy = tf32r(v.y), hz = tf32r(v.z), hw = tf32r(v.w);
            sAh[(k0 + 0) * GPITCH + aRow] = hx;
            sAh[(k0 + 1) * GPITCH + aRow] = hy;
            sAh[(k0 + 2) * GPITCH + aRow] = hz;
            sAh[(k0 + 3) * GPITCH + aRow] = hw;
            sAl[(k0 + 0) * GPITCH + aRow] = tf32r(v.x - hx);
            sAl[(k0 + 1) * GPITCH + aRow] = tf32r(v.y - hy);
            sAl[(k0 + 2) * GPITCH + aRow] = tf32r(v.z - hz);
            sAl[(k0 + 3) * GPITCH + aRow] = tf32r(v.w - hw);
        }
#pragma unroll
        for (int j = 0; j < 4; j++) {
            float4 v = bvr[j];
            float4 hi, lo;
            hi.x = tf32r(v.x); lo.x = tf32r(v.x - hi.x);
            hi.y = tf32r(v.y); lo.y = tf32r(v.y - hi.y);
            hi.z = tf32r(v.z); lo.z = tf32r(v.z - hi.z);
            hi.w = tf32r(v.w); lo.w = tf32r(v.w - hi.w);
            *(float4*)&sBh[bK * GPITCH + bN0 + j * 4] = hi;
            *(float4*)&sBl[bK * GPITCH + bN0 + j * 4] = lo;
        }
        __syncthreads();
        // ---- prefetch slab s+1 (LDG latency overlaps compute below) ----
        if (s + 1 < nslab) {
#pragma unroll
            for (int j = 0; j < 4; j++) {
                avr[j] = aok ? *(const float4*)(aptr + (s + 1) * SLAB + j * 4)
                             : make_float4(0.f, 0.f, 0.f, 0.f);
                bvr[j] = *(const float4*)(bptr + (size_t)(s + 1) * SLAB * N + j * 4);
            }
        }
        // ---- compute 4 k8 steps ----
#pragma unroll
        for (int kk = 0; kk < SLAB; kk += 8) {
            uint32_t ah[2][4], al[2][4];
#pragma unroll
            for (int am = 0; am < 2; am++) {
                int m0 = mw + am * 16 + g;
#pragma unroll
                for (int rr = 0; rr < 4; rr++) {
                    int k = kk + t + ((rr >> 1) << 2);
                    int m = m0 + ((rr & 1) << 3);
                    ah[am][rr] = __float_as_uint(sAh[k * GPITCH + m]);
                    al[am][rr] = __float_as_uint(sAl[k * GPITCH + m]);
                }
            }
#pragma unroll
            for (int an = 0; an < 8; an++) {
                int n = nw + an * 8 + g;
                uint32_t bh[2], bl[2];
#pragma unroll
                for (int rr = 0; rr < 2; rr++) {
                    int k = kk + t + rr * 4;
                    bh[rr] = __float_as_uint(sBh[k * GPITCH + n]);
                    bl[rr] = __float_as_uint(sBl[k * GPITCH + n]);
                }
#pragma unroll
                for (int am = 0; am < 2; am++) {
                    float* cc = &c[(am * 8 + an) * 4];
                    mma_tf32(cc, ah[am], bh);
                    mma_tf32(cc, al[am], bh);
                    mma_tf32(cc, ah[am], bl);
                }
            }
        }
        __syncthreads();
    }

#pragma unroll
    for (int am = 0; am < 2; am++) {
#pragma unroll
        for (int an = 0; an < 8; an++) {
            float* cc = &c[(am * 8 + an) * 4];
            int row0 = brow * 128 + mw + am * 16 + g;
            int col = bcol * 128 + nw + an * 8 + 2 * t;
            float bx = 0.f, by = 0.f;
            if (bias) { bx = bias[col]; by = bias[col + 1]; }
            if (row0 < M) {
                float2 o; o.x = cc[0] + bx; o.y = cc[1] + by;
                *(float2*)(C + (size_t)row0 * N + col) = o;
            }
            if (row0 + 8 < M) {
                float2 o; o.x = cc[2] + bx; o.y = cc[3] + by;
                *(float2*)(C + (size_t)(row0 + 8) * N + col) = o;
            }
        }
    }
}

// ---------------- similarity ----------------
__global__ void sim_kernel(const float* __restrict__ g_info)
{
    int t = blockIdx.x;
    int lane = threadIdx.x & 31, warp = threadIdx.x >> 5;
    __shared__ float wacc[4];
    const float* qrow = g_qkv + (size_t)(t + REG_N) * (3 * CDIM);
    float local = 0.f;
    for (int h = warp; h < HEADS; h += 4) {
        float q0 = qrow[h * DH + lane];
        float q1 = qrow[h * DH + lane + 32];
        float g0 = g_info[h * DH + lane];
        float g1 = g_info[h * DH + lane + 32];
        float d = q0 * g0 + q1 * g1;
        float nq = q0 * q0 + q1 * q1;
        float ng = g0 * g0 + g1 * g1;
#pragma unroll
        for (int o = 16; o > 0; o >>= 1) {
            d  += __shfl_xor_sync(0xffffffffu, d, o);
            nq += __shfl_xor_sync(0xffffffffu, nq, o);
            ng += __shfl_xor_sync(0xffffffffu, ng, o);
        }
        if (lane == 0) local += d / (sqrtf(nq) * sqrtf(ng));
    }
    if (lane == 0) wacc[warp] = local;
    __syncthreads();
    if (threadIdx.x == 0)
        g_sim[t] = (wacc[0] + wacc[1] + wacc[2] + wacc[3]) * (1.0f / 16.0f);
}

// ---------------- minmax + threshold + scan -> key permutation --------------
__global__ void maskscan_kernel()
{
    int tid = threadIdx.x;
    int lane = tid & 31, warp = tid >> 5;
    int t0 = tid * 3;
    float v0 = g_sim[t0], v1 = g_sim[t0 + 1], v2 = g_sim[t0 + 2];
    float mn = fminf(v0, fminf(v1, v2));
    float mx = fmaxf(v0, fmaxf(v1, v2));
#pragma unroll
    for (int o = 16; o > 0; o >>= 1) {
        mn = fminf(mn, __shfl_xor_sync(0xffffffffu, mn, o));
        mx = fmaxf(mx, __shfl_xor_sync(0xffffffffu, mx, o));
    }
    __shared__ float smn[24], smx[24];
    __shared__ float s_bmn, s_bmx;
    if (lane == 0) { smn[warp] = mn; smx[warp] = mx; }
    __syncthreads();
    if (tid == 0) {
        float a = smn[0], b = smx[0];
        for (int w = 1; w < 24; w++) { a = fminf(a, smn[w]); b = fmaxf(b, smx[w]); }
        s_bmn = a; s_bmx = b;
    }
    __syncthreads();
    float bmn = s_bmn;
    float inv = 1.0f / (s_bmx - bmn);
    int f[3]; int c = 0;
    f[0] = ((v0 - bmn) * inv > 0.9f) ? 1 : 0;
    f[1] = ((v1 - bmn) * inv > 0.9f) ? 1 : 0;
    f[2] = ((v2 - bmn) * inv > 0.9f) ? 1 : 0;
#pragma unroll
    for (int e = 0; e < 3; e++) {
        c += f[e];
        g_flag[t0 + e] = (unsigned char)f[e];
    }
    int incl = c;
#pragma unroll
    for (int o = 1; o < 32; o <<= 1) {
        int v = __shfl_up_sync(0xffffffffu, incl, o);
        if (lane >= o) incl += v;
    }
    __shared__ int wsum[24];
    __shared__ int s_npos;
    if (lane == 31) wsum[warp] = incl;
    __syncthreads();
    if (tid == 0) {
        int acc = 0;
        for (int w = 0; w < 24; w++) { int v = wsum[w]; wsum[w] = acc; acc += v; }
        s_npos = acc;
        g_npos[0] = acc;
        for (int i = 0; i < REG_N; i++) g_perm[i] = i;
    }
    __syncthreads();
    int excl = incl - c + wsum[warp];
    int npos = s_npos;
    int pp = excl;
#pragma unroll
    for (int e = 0; e < 3; e++) {
        int t = t0 + e;
        if (f[e]) { g_perm[REG_N + pp] = t + REG_N; pp++; }
        else      { g_perm[REG_N + npos + (t - pp)] = t + REG_N; }
    }
}

// ================== helpers ==================
__device__ __forceinline__ float bf16rt(float x)
{
    __nv_bfloat16 h = __float2bfloat16(x);
    return __bfloat162float(h);
}
__device__ __forceinline__ uint32_t pack2(float lo, float hi)
{
    uint32_t r;
    asm("cvt.rn.bf16x2.f32 %0, %1, %2;" : "=r"(r) : "f"(hi), "f"(lo));
    return r;
}
__device__ __forceinline__ void mma16816(float* d, const uint32_t* a, const uint32_t* b)
{
    asm volatile(
        "mma.sync.aligned.m16n8k16.row.col.f32.bf16.bf16.f32 "
        "{%0,%1,%2,%3},{%4,%5,%6,%7},{%8,%9},{%0,%1,%2,%3};"
        : "+f"(d[0]), "+f"(d[1]), "+f"(d[2]), "+f"(d[3])
        : "r"(a[0]), "r"(a[1]), "r"(a[2]), "r"(a[3]), "r"(b[0]), "r"(b[1]));
}
__device__ __forceinline__ uint32_t smem_u32(const void* p)
{
    uint32_t a;
    asm("{ .reg .u64 t; cvta.to.shared.u64 t, %1; cvt.u32.u64 %0, t; }" : "=r"(a) : "l"(p));
    return a;
}

// ============ pre-convert: permuted K / V^T -> bf16 hi/lo fragment layout ====
__global__ __launch_bounds__(256) void preconv_kernel(int /*dummy*/)
{
    __shared__ __nv_bfloat16 sVH[64][66];
    __shared__ __nv_bfloat16 sVL[64][66];
    int tile = blockIdx.x, h = blockIdx.y;
    int tid = threadIdx.x;
    int keyl = tid >> 2, grp = tid & 3;
    int kidx = tile * 64 + keyl;
    bool ok = kidx < N_TOK;
    int src = ok ? g_perm[kidx] : 0;
    const float* kr = g_qkv + (size_t)src * (3 * CDIM) + CDIM + h * DH + grp * 16;
    const float* vr = kr + CDIM;

    float kb[16], vb[16];
#pragma unroll
    for (int j = 0; j < 4; j++) {
        float4 kv = ok ? *(const float4*)(kr + j * 4) : make_float4(0.f, 0.f, 0.f, 0.f);
        float4 vv = ok ? *(const float4*)(vr + j * 4) : make_float4(0.f, 0.f, 0.f, 0.f);
        kb[j * 4 + 0] = kv.x; kb[j * 4 + 1] = kv.y; kb[j * 4 + 2] = kv.z; kb[j * 4 + 3] = kv.w;
        vb[j * 4 + 0] = vv.x; vb[j * 4 + 1] = vv.y; vb[j * 4 + 2] = vv.z; vb[j * 4 + 3] = vv.w;
    }
    uint32_t* kout = &g_kc[h][kidx][grp * 16];
#pragma unroll
    for (int pj = 0; pj < 8; pj++) {
        float a = kb[2 * pj], b = kb[2 * pj + 1];
        float ha = bf16rt(a), hb = bf16rt(b);
        int sh = 4 * (pj & 3) + (pj >> 2);
        kout[sh] = pack2(ha, hb);
        kout[sh + 2] = pack2(a - ha, b - hb);
    }
#pragma unroll
    for (int d = 0; d < 16; d++) {
        float v = vb[d];
        float hv = bf16rt(v);
        sVH[grp * 16 + d][keyl] = __float2bfloat16(v);
        sVL[grp * 16 + d][keyl] = __float2bfloat16(v - hv);
    }
    __syncthreads();
    int dim = tid >> 2, grp2 = tid & 3;
    uint32_t* vout = &g_vtc[h][dim][tile * 64 + grp2 * 16];
#pragma unroll
    for (int pj = 0; pj < 8; pj++) {
        int k0 = grp2 * 16 + 2 * pj;
        uint32_t hi = ((uint32_t)__bfloat16_as_ushort(sVH[dim][k0 + 1]) << 16)
                    | __bfloat16_as_ushort(sVH[dim][k0]);
        uint32_t lo = ((uint32_t)__bfloat16_as_ushort(sVL[dim][k0 + 1]) << 16)
                    | __bfloat16_as_ushort(sVL[dim][k0]);
        int sh = 4 * (pj & 3) + (pj >> 2);
        vout[sh] = hi;
        vout[sh + 2] = lo;
    }
}

// ================== tensor-core flash attention (bf16x3, cp.async) ===========
// R8 configuration: 256-thread CTA, 64 query rows, 1 CTA/SM (proven optimum).
#define FS_STAGE_U32 8704           // K 64*68 + VT 64*68
#define FS_STAGE_BYTES (FS_STAGE_U32 * 4)
#define FS_RED_U32 (2 * FS_STAGE_U32)
#define FS_TOTAL_BYTES ((FS_RED_U32 + 448) * 4)

__device__ __forceinline__ void copy_tile(uint32_t dstb, int ti, int h, int tid)
{
    int row = tid >> 2, seg = tid & 3;
    uint32_t kd = dstb + (uint32_t)(row * 68 + seg * 16) * 4;
    const uint32_t* ksp = &g_kc[h][ti * 64 + row][seg * 16];
    uint32_t vd = dstb + (uint32_t)(4352 + row * 68 + seg * 16) * 4;
    const uint32_t* vsp = &g_vtc[h][row][ti * 64 + seg * 16];
#pragma unroll
    for (int c = 0; c < 4; c++) {
        asm volatile("cp.async.ca.shared.global [%0], [%1], 16;"
                     :: "r"(kd + c * 16), "l"(ksp + c * 4) : "memory");
        asm volatile("cp.async.ca.shared.global [%0], [%1], 16;"
                     :: "r"(vd + c * 16), "l"(vsp + c * 4) : "memory");
    }
}

#define PAIR_BAR(mi) asm volatile("bar.sync %0, 64;" :: "r"((mi) + 1) : "memory")

template <int GRP>
__device__ __forceinline__ void group_pass(
    float sacc[4][4], float o[8][4], const uint32_t* Vb,
    float* red0, float* red1, float* s_m, float* s_l, float* s_al,
    int base, int pend, int tid, int g, int t, int mi, int hf)
{
    int r0 = mi * 16 + g, r1 = r0 + 8;
    float pm0 = -1e30f, pm1 = -1e30f;
#pragma unroll
    for (int nj = 0; nj < 4; nj++) {
        int kc = base + (hf * 4 + nj) * 8 + 2 * t;
        bool in0 = (GRP == 0) ? (kc < pend)
                              : ((kc < REG_N) || (kc >= pend && kc < N_TOK));
        bool in1 = (GRP == 0) ? (kc + 1 < pend)
                              : ((kc + 1 < REG_N) || (kc + 1 >= pend && kc + 1 < N_TOK));
        if (in0) { pm0 = fmaxf(pm0, sacc[nj][0]); pm1 = fmaxf(pm1, sacc[nj][2]); }
        if (in1) { pm0 = fmaxf(pm0, sacc[nj][1]); pm1 = fmaxf(pm1, sacc[nj][3]); }
    }
    pm0 = fmaxf(pm0, __shfl_xor_sync(0xffffffffu, pm0, 1));
    pm0 = fmaxf(pm0, __shfl_xor_sync(0xffffffffu, pm0, 2));
    pm1 = fmaxf(pm1, __shfl_xor_sync(0xffffffffu, pm1, 1));
    pm1 = fmaxf(pm1, __shfl_xor_sync(0xffffffffu, pm1, 2));
    if (t == 0) {
        float* rd = hf ? red1 : red0;
        rd[r0] = pm0; rd[r1] = pm1;
    }
    PAIR_BAR(mi);
    if (hf == 0 && t == 0) {
#pragma unroll
        for (int rr = 0; rr < 2; rr++) {
            int r = rr ? r1 : r0;
            float mt = fmaxf(red0[r], red1[r]);
            float mo = s_m[r];
            float mn2 = fmaxf(mo, mt);
            s_al[r] = __expf(mo - mn2);
            s_m[r] = mn2;
        }
    }
    PAIR_BAR(mi);
    float m0 = s_m[r0], m1 = s_m[r1];
    float p[4][4];
    float ps0 = 0.f, ps1 = 0.f;
#pragma unroll
    for (int nj = 0; nj < 4; nj++) {
        int kc = base + (hf * 4 + nj) * 8 + 2 * t;
        bool in0 = (GRP == 0) ? (kc < pend)
                              : ((kc < REG_N) || (kc >= pend && kc < N_TOK));
        bool in1 = (GRP == 0) ? (kc + 1 < pend)
                              : ((kc + 1 < REG_N) || (kc + 1 >= pend && kc + 1 < N_TOK));
        p[nj][0] = in0 ? __expf(sacc[nj][0] - m0) : 0.f;
        p[nj][1] = in1 ? __expf(sacc[nj][1] - m0) : 0.f;
        p[nj][2] = in0 ? __expf(sacc[nj][2] - m1) : 0.f;
        p[nj][3] = in1 ? __expf(sacc[nj][3] - m1) : 0.f;
        ps0 += p[nj][0] + p[nj][1];
        ps1 += p[nj][2] + p[nj][3];
    }
    ps0 += __shfl_xor_sync(0xffffffffu, ps0, 1);
    ps0 += __shfl_xor_sync(0xffffffffu, ps0, 2);
    ps1 += __shfl_xor_sync(0xffffffffu, ps1, 1);
    ps1 += __shfl_xor_sync(0xffffffffu, ps1, 2);
    if (t == 0) {
        float* rd = hf ? red1 : red0;
        rd[r0] = ps0; rd[r1] = ps1;
    }
    PAIR_BAR(mi);
    if (hf == 0 && t == 0) {
        s_l[r0] = s_l[r0] * s_al[r0] + red0[r0] + red1[r0];
        s_l[r1] = s_l[r1] * s_al[r1] + red0[r1] + red1[r1];
    }
    PAIR_BAR(mi);
    float al0 = s_al[r0], al1 = s_al[r1];
#pragma unroll
    for (int nd = 0; nd < 8; nd++) {
        o[nd][0] *= al0; o[nd][1] *= al0;
        o[nd][2] *= al1; o[nd][3] *= al1;
    }
    uint32_t ah[2][4], alo[2][4];
#pragma unroll
    for (int ks = 0; ks < 2; ks++) {
        float h00 = bf16rt(p[2 * ks][0]),     h01 = bf16rt(p[2 * ks][1]);
        float h02 = bf16rt(p[2 * ks][2]),     h03 = bf16rt(p[2 * ks][3]);
        float h10 = bf16rt(p[2 * ks + 1][0]), h11 = bf16rt(p[2 * ks + 1][1]);
        float h12 = bf16rt(p[2 * ks + 1][2]), h13 = bf16rt(p[2 * ks + 1][3]);
        ah[ks][0] = pack2(h00, h01);
        ah[ks][1] = pack2(h02, h03);
        ah[ks][2] = pack2(h10, h11);
        ah[ks][3] = pack2(h12, h13);
        alo[ks][0] = pack2(p[2 * ks][0] - h00,     p[2 * ks][1] - h01);
        alo[ks][1] = pack2(p[2 * ks][2] - h02,     p[2 * ks][3] - h03);
        alo[ks][2] = pack2(p[2 * ks + 1][0] - h10, p[2 * ks + 1][1] - h11);
        alo[ks][3] = pack2(p[2 * ks + 1][2] - h12, p[2 * ks + 1][3] - h13);
    }
#pragma unroll
    for (int nd = 0; nd < 8; nd++) {
        int db = (nd * 8 + g) * 68;
#pragma unroll
        for (int ks = 0; ks < 2; ks++) {
            uint4 vv = *(const uint4*)&Vb[db + (2 * hf + ks) * 16 + 4 * t];
            uint32_t bh[2] = { vv.x, vv.y };
            uint32_t bl[2] = { vv.z, vv.w };
            mma16816(o[nd], ah[ks], bh);
            mma16816(o[nd], alo[ks], bh);
            mma16816(o[nd], ah[ks], bl);
        }
    }
}

__global__ void __launch_bounds__(256) flash_kernel(int /*dummy*/)
{
    extern __shared__ char smc[];
    uint32_t* su = (uint32_t*)smc;
    float* fred = (float*)smc + FS_RED_U32;
    float* red0 = fred;
    float* red1 = fred + 64;
    float* s_mp = fred + 128;
    float* s_lp = fred + 192;
    float* s_mn = fred + 256;
    float* s_ln = fred + 320;
    float* s_al = fred + 384;

    int tid = threadIdx.x;
    int warp = tid >> 5, lane = tid & 31;
    int g = lane >> 2, t = lane & 3;
    int mi = warp >> 1, hf = warp & 1;
    int h = blockIdx.y, qt = blockIdx.x;
    int qbase = qt * 64;
    int pend = REG_N + g_npos[0];
    uint32_t sbyte = smem_u32(smc);

    // Q fragments (hi/lo bf16), scaled
    uint32_t Qh[4][4], Ql[4][4];
    {
        int r0g = qbase + mi * 16 + g;
        int r1g = r0g + 8;
        bool ok0 = r0g < N_TOK, ok1 = r1g < N_TOK;
        const float* q0p = g_qkv + (size_t)r0g * (3 * CDIM) + h * DH;
        const float* q1p = g_qkv + (size_t)r1g * (3 * CDIM) + h * DH;
#pragma unroll
        for (int ks = 0; ks < 4; ks++) {
            int d0 = ks * 16 + 2 * t;
            float2 x0 = ok0 ? *(const float2*)(q0p + d0) : make_float2(0.f, 0.f);
            float2 x1 = ok1 ? *(const float2*)(q1p + d0) : make_float2(0.f, 0.f);
            float2 x2 = ok0 ? *(const float2*)(q0p + d0 + 8) : make_float2(0.f, 0.f);
            float2 x3 = ok1 ? *(const float2*)(q1p + d0 + 8) : make_float2(0.f, 0.f);
            x0.x *= SCALE; x0.y *= SCALE; x1.x *= SCALE; x1.y *= SCALE;
            x2.x *= SCALE; x2.y *= SCALE; x3.x *= SCALE; x3.y *= SCALE;
            float h0x = bf16rt(x0.x), h0y = bf16rt(x0.y);
            float h1x = bf16rt(x1.x), h1y = bf16rt(x1.y);
            float h2x = bf16rt(x2.x), h2y = bf16rt(x2.y);
            float h3x = bf16rt(x3.x), h3y = bf16rt(x3.y);
            Qh[ks][0] = pack2(h0x, h0y); Ql[ks][0] = pack2(x0.x - h0x, x0.y - h0y);
            Qh[ks][1] = pack2(h1x, h1y); Ql[ks][1] = pack2(x1.x - h1x, x1.y - h1y);
            Qh[ks][2] = pack2(h2x, h2y); Ql[ks][2] = pack2(x2.x - h2x, x2.y - h2y);
            Qh[ks][3] = pack2(h3x, h3y); Ql[ks][3] = pack2(x3.x - h3x, x3.y - h3y);
        }
    }
    if (tid < 64) {
        s_mp[tid] = -1e30f; s_lp[tid] = 0.f;
        s_mn[tid] = -1e30f; s_ln[tid] = 0.f;
    }
    float o[2][8][4];
#pragma unroll
    for (int gi = 0; gi < 2; gi++)
#pragma unroll
        for (int nd = 0; nd < 8; nd++)
#pragma unroll
            for (int e = 0; e < 4; e++) o[gi][nd][e] = 0.f;

    // preload tile 0
    copy_tile(sbyte, 0, h, tid);
    asm volatile("cp.async.commit_group;" ::: "memory");

    for (int ti = 0; ti < NTILE; ti++) {
        if (ti + 1 < NTILE) {
            copy_tile(sbyte + ((ti + 1) & 1) * FS_STAGE_BYTES, ti + 1, h, tid);
            asm volatile("cp.async.commit_group;" ::: "memory");
            asm volatile("cp.async.wait_group 1;" ::: "memory");
        } else {
            asm volatile("cp.async.wait_group 0;" ::: "memory");
        }
        __syncthreads();
        const uint32_t* Kb = su + (ti & 1) * FS_STAGE_U32;
        const uint32_t* Vb = Kb + 4352;
        int base = ti * 64;

        float sacc[4][4];
#pragma unroll
        for (int nj = 0; nj < 4; nj++)
#pragma unroll
            for (int e = 0; e < 4; e++) sacc[nj][e] = 0.f;
#pragma unroll
        for (int nj = 0; nj < 4; nj++) {
            int keyb = ((hf * 4 + nj) * 8 + g) * 68;
#pragma unroll
            for (int ks = 0; ks < 4; ks++) {
                uint4 kv = *(const uint4*)&Kb[keyb + ks * 16 + 4 * t];
                uint32_t bh[2] = { kv.x, kv.y };
                uint32_t bl[2] = { kv.z, kv.w };
                mma16816(sacc[nj], Qh[ks], bh);
                mma16816(sacc[nj], Ql[ks], bh);
                mma16816(sacc[nj], Qh[ks], bl);
            }
        }
        bool runPos = base < pend;
        bool runNeg = (base < REG_N) || (base + 64 > pend);
        if (runPos)
            group_pass<0>(sacc, o[0], Vb, red0, red1,
                          s_mp, s_lp, s_al, base, pend, tid, g, t, mi, hf);
        if (runNeg)
            group_pass<1>(sacc, o[1], Vb, red0, red1,
                          s_mn, s_ln, s_al, base, pend, tid, g, t, mi, hf);
        __syncthreads();
    }

    // ---- epilogue: combine warp halves, normalize, pos/neg select ----
    float* PB = (float*)smc;
    float* NB = PB + 64 * 72;
    int r0 = mi * 16 + g, r1 = r0 + 8;
    if (hf == 1) {
#pragma unroll
        for (int nd = 0; nd < 8; nd++) {
            int c = nd * 8 + 2 * t;
            *(float2*)&PB[r0 * 72 + c] = make_float2(o[0][nd][0], o[0][nd][1]);
            *(float2*)&PB[r1 * 72 + c] = make_float2(o[0][nd][2], o[0][nd][3]);
            *(float2*)&NB[r0 * 72 + c] = make_float2(o[1][nd][0], o[1][nd][1]);
            *(float2*)&NB[r1 * 72 + c] = make_float2(o[1][nd][2], o[1][nd][3]);
        }
    }
    __syncthreads();
    if (hf == 0) {
        int q0 = qbase + r0, q1 = qbase + r1;
        float invlp0 = 1.f / s_lp[r0], invlp1 = 1.f / s_lp[r1];
        float invln0 = 1.f / s_ln[r0], invln1 = 1.f / s_ln[r1];
        bool reg0 = q0 < REG_N, reg1 = q1 < REG_N;
        float fl0 = (q0 >= REG_N && q0 < N_TOK) ? (g_flag[q0 - REG_N] ? 1.f : 0.f) : 0.f;
        float fl1 = (q1 >= REG_N && q1 < N_TOK) ? (g_flag[q1 - REG_N] ? 1.f : 0.f) : 0.f;
#pragma unroll
        for (int nd = 0; nd < 8; nd++) {
            int c = nd * 8 + 2 * t;
            float2 pp0 = *(float2*)&PB[r0 * 72 + c];
            float2 pp1 = *(float2*)&PB[r1 * 72 + c];
            float2 nn0 = *(float2*)&NB[r0 * 72 + c];
            float2 nn1 = *(float2*)&NB[r1 * 72 + c];
            float opx = (o[0][nd][0] + pp0.x) * invlp0;
            float opy = (o[0][nd][1] + pp0.y) * invlp0;
            float onx = (o[1][nd][0] + nn0.x) * invln0;
            float ony = (o[1][nd][1] + nn0.y) * invln0;
            float vx, vy;
            if (reg0) { vx = 0.5f * (opx + onx); vy = 0.5f * (opy + ony); }
            else      { vx = fl0 ? opx : onx;    vy = fl0 ? opy : ony; }
            if (q0 < N_TOK)
                *(float2*)(g_attn + (size_t)q0 * CDIM + h * DH + c) = make_float2(vx, vy);
            float opx1 = (o[0][nd][2] + pp1.x) * invlp1;
            float opy1 = (o[0][nd][3] + pp1.y) * invlp1;
            float onx1 = (o[1][nd][2] + nn1.x) * invln1;
            float ony1 = (o[1][nd][3] + nn1.y) * invln1;
            float wx, wy;
            if (reg1) { wx = 0.5f * (opx1 + onx1); wy = 0.5f * (opy1 + ony1); }
            else      { wx = fl1 ? opx1 : onx1;    wy = fl1 ? opy1 : ony1; }
            if (q1 < N_TOK)
                *(float2*)(g_attn + (size_t)q1 * CDIM + h * DH + c) = make_float2(wx, wy);
        }
    }
}

// ---------------- launcher ----------------
extern "C" void kernel_launch(void* const* d_in, const int* in_sizes, int n_in,
                              void* d_out, int out_size)
{
    const float* x = nullptr; const float* ginfo = nullptr;
    const float* wqkv = nullptr; const float* wproj = nullptr;
    const float* bproj = nullptr;
    for (int i = 0; i < n_in; i++) {
        switch (in_sizes[i]) {
            case N_TOK * CDIM:      x = (const float*)d_in[i]; break;
            case 12 * 2 * CDIM:     ginfo = (const float*)d_in[i]; break;
            case CDIM * 3 * CDIM:   wqkv = (const float*)d_in[i]; break;
            case CDIM * CDIM:       wproj = (const float*)d_in[i]; break;
            case CDIM:              bproj = (const float*)d_in[i]; break;
        }
    }
    float* out = (float*)d_out;

    float* qkv;  cudaGetSymbolAddress((void**)&qkv,  g_qkv);
    float* attn; cudaGetSymbolAddress((void**)&attn, g_attn);

    int gsmem = GEMM_SMEM_FLOATS * (int)sizeof(float);
    cudaFuncSetAttribute(gemm_mma, cudaFuncAttributeMaxDynamicSharedMemorySize, gsmem);
    cudaFuncSetAttribute(flash_kernel, cudaFuncAttributeMaxDynamicSharedMemorySize,
                         FS_TOTAL_BYTES);

    // [1] QKV GEMM (tf32 mma x3, reg-pipelined)
    gemm_mma<<<dim3(3 * CDIM / 128, (N_TOK + 127) / 128), 256, gsmem>>>(
        x, wqkv, nullptr, qkv, N_TOK, 3 * CDIM, CDIM);
    // [2] similarity
    sim_kernel<<<N_T, 128>>>(ginfo);
    // [3] minmax + mask + scan
    maskscan_kernel<<<1, 768>>>();
    // [4] pre-convert permuted K / V^T to bf16 hi/lo fragment layout
    preconv_kernel<<<dim3(NTILE, HEADS), 256>>>(0);
    // [5] flash attention (R8 config: 256 threads, cp.async double-buffered)
    flash_kernel<<<dim3(NTILE, HEADS), 256, FS_TOTAL_BYTES>>>(0);
    // [6] projection GEMM + bias (reg-pipelined)
    gemm_mma<<<dim3(CDIM / 128, (N_TOK + 127) / 128), 256, gsmem>>>(
        attn, wproj, bproj, out, N_TOK, CDIM, CDIM);
}

// round 11
// speedup vs baseline: 1.5484x; 1.1228x over previous
#include <cuda_runtime.h>
#include <cuda_bf16.h>
#include <math.h>
#include <stdint.h>

#define N_TOK 2309
#define N_T   2304
#define CDIM  1024
#define HEADS 16
#define DH    64
#define REG_N 5
#define SCALE 0.125f   // 64^-0.5
#define NTILE 37
#define KEYPAD (NTILE * 64)   // 2368

// ---------------- device scratch (static, no runtime alloc) ----------------
__device__ float g_qkv[(size_t)N_TOK * 3 * CDIM];
__device__ float g_attn[(size_t)N_TOK * CDIM];
__device__ float g_sim[N_T];
__device__ int   g_perm[N_TOK];
__device__ int   g_npos[1];
__device__ unsigned char g_flag[N_T];
// pre-converted bf16 hi/lo, permuted keys, fragment-ready layout
__device__ uint32_t g_kc [HEADS][KEYPAD][64];   // [head][key][slot]
__device__ uint32_t g_vtc[HEADS][DH][KEYPAD];   // [head][dim][tile*64+slot]

// ========== tf32x3 MMA GEMM, cp.async double-buffered raw-f32 smem ==========
// A: M x K row-major -> smem [128][36] (row-major, pad 36)
// B: K x N row-major -> smem [32][136] (k-major, pad 136)
// hi/lo tf32 split done at fragment-load time (bit-identical to stored split).
#define SLAB 32
#define GA_PITCH 36
#define GB_PITCH 136
#define G_STAGEF (128 * GA_PITCH + SLAB * GB_PITCH)   // 8960 floats
#define G_STAGEB (G_STAGEF * 4)                        // 35840 bytes
#define G_BOFF  (128 * GA_PITCH)                       // float offset of B
#define GEMM_SMEM_BYTES (2 * G_STAGEB)                 // 71680

__device__ __forceinline__ float tf32r(float v)
{
    uint32_t u;
    asm("cvt.rna.tf32.f32 %0, %1;" : "=r"(u) : "f"(v));
    return __uint_as_float(u);
}

__device__ __forceinline__ void mma_tf32(float* d, const uint32_t* a, const uint32_t* b)
{
    asm volatile(
        "mma.sync.aligned.m16n8k8.row.col.f32.tf32.tf32.f32 "
        "{%0,%1,%2,%3}, {%4,%5,%6,%7}, {%8,%9}, {%0,%1,%2,%3};"
        : "+f"(d[0]), "+f"(d[1]), "+f"(d[2]), "+f"(d[3])
        : "r"(a[0]), "r"(a[1]), "r"(a[2]), "r"(a[3]), "r"(b[0]), "r"(b[1]));
}

__device__ __forceinline__ uint32_t smem_u32(const void* p)
{
    uint32_t a;
    asm("{ .reg .u64 t; cvta.to.shared.u64 t, %1; cvt.u32.u64 %0, t; }" : "=r"(a) : "l"(p));
    return a;
}

__global__ __launch_bounds__(256) void gemm_mma(
    const float* __restrict__ A, const float* __restrict__ B,
    const float* __restrict__ bias, float* __restrict__ C,
    int M, int N, int K)
{
    extern __shared__ float sm[];
    uint32_t sbyte = smem_u32(sm);

    int tid = threadIdx.x;
    int warp = tid >> 5, lane = tid & 31;
    int g = lane >> 2, t = lane & 3;
    int mw = (warp >> 1) * 32;
    int nw = (warp & 1) * 64;
    int brow = blockIdx.y, bcol = blockIdx.x;

    // A copy mapping: 2 threads per row, 16 floats each
    int aRow = tid >> 1;
    int aCol0 = (tid & 1) * 16;
    int aRowG = brow * 128 + aRow;
    bool aok = aRowG < M;
    const float* aptr = A + (size_t)aRowG * K + aCol0;
    uint32_t aDst = (uint32_t)(aRow * GA_PITCH + aCol0) * 4;
    // B copy mapping: 8 threads per k-row, 16 floats each
    int bRow = tid >> 3;
    int bCol0 = (tid & 7) * 16;
    const float* bptr = B + (size_t)bRow * N + bcol * 128 + bCol0;
    uint32_t bDst = (uint32_t)(G_BOFF + bRow * GB_PITCH + bCol0) * 4;

    float c[64];
#pragma unroll
    for (int i = 0; i < 64; i++) c[i] = 0.f;

    int nslab = K / SLAB;

    // ---- prologue: async copy slab 0 into stage 0 ----
    {
        uint32_t base = sbyte;
#pragma unroll
        for (int cch = 0; cch < 4; cch++) {
            if (aok) {
                asm volatile("cp.async.ca.shared.global [%0], [%1], 16;"
                             :: "r"(base + aDst + cch * 16), "l"(aptr + cch * 4) : "memory");
            } else {
                asm volatile("st.shared.v4.b32 [%0], {%1,%1,%1,%1};"
                             :: "r"(base + aDst + cch * 16), "r"(0) : "memory");
            }
            asm volatile("cp.async.ca.shared.global [%0], [%1], 16;"
                         :: "r"(base + bDst + cch * 16), "l"(bptr + cch * 4) : "memory");
        }
        asm volatile("cp.async.commit_group;" ::: "memory");
    }

    for (int s = 0; s < nslab; s++) {
        // ---- prefetch slab s+1 into other stage (no registers held) ----
        if (s + 1 < nslab) {
            uint32_t base = sbyte + ((s + 1) & 1) * G_STAGEB;
            const float* ap = aptr + (s + 1) * SLAB;
            const float* bp = bptr + (size_t)(s + 1) * SLAB * N;
#pragma unroll
            for (int cch = 0; cch < 4; cch++) {
                if (aok) {
                    asm volatile("cp.async.ca.shared.global [%0], [%1], 16;"
                                 :: "r"(base + aDst + cch * 16), "l"(ap + cch * 4) : "memory");
                } else {
                    asm volatile("st.shared.v4.b32 [%0], {%1,%1,%1,%1};"
                                 :: "r"(base + aDst + cch * 16), "r"(0) : "memory");
                }
                asm volatile("cp.async.ca.shared.global [%0], [%1], 16;"
                             :: "r"(base + bDst + cch * 16), "l"(bp + cch * 4) : "memory");
            }
            asm volatile("cp.async.commit_group;" ::: "memory");
            asm volatile("cp.async.wait_group 1;" ::: "memory");
        } else {
            asm volatile("cp.async.wait_group 0;" ::: "memory");
        }
        __syncthreads();

        const float* sA = sm + (s & 1) * G_STAGEF;
        const float* sB = sA + G_BOFF;

        // ---- compute 4 k8 steps, hi/lo split at fragment load ----
#pragma unroll
        for (int kk = 0; kk < SLAB; kk += 8) {
            uint32_t ah[2][4], al[2][4];
#pragma unroll
            for (int am = 0; am < 2; am++) {
#pragma unroll
                for (int rr = 0; rr < 4; rr++) {
                    int m = mw + am * 16 + g + ((rr & 1) << 3);
                    int k = kk + t + ((rr >> 1) << 2);
                    float v = sA[m * GA_PITCH + k];
                    float hi = tf32r(v);
                    ah[am][rr] = __float_as_uint(hi);
                    al[am][rr] = __float_as_uint(tf32r(v - hi));
                }
            }
#pragma unroll
            for (int an = 0; an < 8; an++) {
                int n = nw + an * 8 + g;
                uint32_t bh[2], bl[2];
#pragma unroll
                for (int rr = 0; rr < 2; rr++) {
                    int k = kk + t + rr * 4;
                    float v = sB[k * GB_PITCH + n];
                    float hi = tf32r(v);
                    bh[rr] = __float_as_uint(hi);
                    bl[rr] = __float_as_uint(tf32r(v - hi));
                }
#pragma unroll
                for (int am = 0; am < 2; am++) {
                    float* cc = &c[(am * 8 + an) * 4];
                    mma_tf32(cc, ah[am], bh);
                    mma_tf32(cc, al[am], bh);
                    mma_tf32(cc, ah[am], bl);
                }
            }
        }
        __syncthreads();
    }

#pragma unroll
    for (int am = 0; am < 2; am++) {
#pragma unroll
        for (int an = 0; an < 8; an++) {
            float* cc = &c[(am * 8 + an) * 4];
            int row0 = brow * 128 + mw + am * 16 + g;
            int col = bcol * 128 + nw + an * 8 + 2 * t;
            float bx = 0.f, by = 0.f;
            if (bias) { bx = bias[col]; by = bias[col + 1]; }
            if (row0 < M) {
                float2 o; o.x = cc[0] + bx; o.y = cc[1] + by;
                *(float2*)(C + (size_t)row0 * N + col) = o;
            }
            if (row0 + 8 < M) {
                float2 o; o.x = cc[2] + bx; o.y = cc[3] + by;
                *(float2*)(C + (size_t)(row0 + 8) * N + col) = o;
            }
        }
    }
}

// ---------------- similarity ----------------
__global__ void sim_kernel(const float* __restrict__ g_info)
{
    int t = blockIdx.x;
    int lane = threadIdx.x & 31, warp = threadIdx.x >> 5;
    __shared__ float wacc[4];
    const float* qrow = g_qkv + (size_t)(t + REG_N) * (3 * CDIM);
    float local = 0.f;
    for (int h = warp; h < HEADS; h += 4) {
        float q0 = qrow[h * DH + lane];
        float q1 = qrow[h * DH + lane + 32];
        float g0 = g_info[h * DH + lane];
        float g1 = g_info[h * DH + lane + 32];
        float d = q0 * g0 + q1 * g1;
        float nq = q0 * q0 + q1 * q1;
        float ng = g0 * g0 + g1 * g1;
#pragma unroll
        for (int o = 16; o > 0; o >>= 1) {
            d  += __shfl_xor_sync(0xffffffffu, d, o);
            nq += __shfl_xor_sync(0xffffffffu, nq, o);
            ng += __shfl_xor_sync(0xffffffffu, ng, o);
        }
        if (lane == 0) local += d / (sqrtf(nq) * sqrtf(ng));
    }
    if (lane == 0) wacc[warp] = local;
    __syncthreads();
    if (threadIdx.x == 0)
        g_sim[t] = (wacc[0] + wacc[1] + wacc[2] + wacc[3]) * (1.0f / 16.0f);
}

// ---------------- minmax + threshold + scan -> key permutation --------------
__global__ void maskscan_kernel()
{
    int tid = threadIdx.x;
    int lane = tid & 31, warp = tid >> 5;
    int t0 = tid * 3;
    float v0 = g_sim[t0], v1 = g_sim[t0 + 1], v2 = g_sim[t0 + 2];
    float mn = fminf(v0, fminf(v1, v2));
    float mx = fmaxf(v0, fmaxf(v1, v2));
#pragma unroll
    for (int o = 16; o > 0; o >>= 1) {
        mn = fminf(mn, __shfl_xor_sync(0xffffffffu, mn, o));
        mx = fmaxf(mx, __shfl_xor_sync(0xffffffffu, mx, o));
    }
    __shared__ float smn[24], smx[24];
    __shared__ float s_bmn, s_bmx;
    if (lane == 0) { smn[warp] = mn; smx[warp] = mx; }
    __syncthreads();
    if (tid == 0) {
        float a = smn[0], b = smx[0];
        for (int w = 1; w < 24; w++) { a = fminf(a, smn[w]); b = fmaxf(b, smx[w]); }
        s_bmn = a; s_bmx = b;
    }
    __syncthreads();
    float bmn = s_bmn;
    float inv = 1.0f / (s_bmx - bmn);
    int f[3]; int c = 0;
    f[0] = ((v0 - bmn) * inv > 0.9f) ? 1 : 0;
    f[1] = ((v1 - bmn) * inv > 0.9f) ? 1 : 0;
    f[2] = ((v2 - bmn) * inv > 0.9f) ? 1 : 0;
#pragma unroll
    for (int e = 0; e < 3; e++) {
        c += f[e];
        g_flag[t0 + e] = (unsigned char)f[e];
    }
    int incl = c;
#pragma unroll
    for (int o = 1; o < 32; o <<= 1) {
        int v = __shfl_up_sync(0xffffffffu, incl, o);
        if (lane >= o) incl += v;
    }
    __shared__ int wsum[24];
    __shared__ int s_npos;
    if (lane == 31) wsum[warp] = incl;
    __syncthreads();
    if (tid == 0) {
        int acc = 0;
        for (int w = 0; w < 24; w++) { int v = wsum[w]; wsum[w] = acc; acc += v; }
        s_npos = acc;
        g_npos[0] = acc;
        for (int i = 0; i < REG_N; i++) g_perm[i] = i;
    }
    __syncthreads();
    int excl = incl - c + wsum[warp];
    int npos = s_npos;
    int pp = excl;
#pragma unroll
    for (int e = 0; e < 3; e++) {
        int t = t0 + e;
        if (f[e]) { g_perm[REG_N + pp] = t + REG_N; pp++; }
        else      { g_perm[REG_N + npos + (t - pp)] = t + REG_N; }
    }
}

// ================== helpers ==================
__device__ __forceinline__ float bf16rt(float x)
{
    __nv_bfloat16 h = __float2bfloat16(x);
    return __bfloat162float(h);
}
__device__ __forceinline__ uint32_t pack2(float lo, float hi)
{
    uint32_t r;
    asm("cvt.rn.bf16x2.f32 %0, %1, %2;" : "=r"(r) : "f"(hi), "f"(lo));
    return r;
}
__device__ __forceinline__ void mma16816(float* d, const uint32_t* a, const uint32_t* b)
{
    asm volatile(
        "mma.sync.aligned.m16n8k16.row.col.f32.bf16.bf16.f32 "
        "{%0,%1,%2,%3},{%4,%5,%6,%7},{%8,%9},{%0,%1,%2,%3};"
        : "+f"(d[0]), "+f"(d[1]), "+f"(d[2]), "+f"(d[3])
        : "r"(a[0]), "r"(a[1]), "r"(a[2]), "r"(a[3]), "r"(b[0]), "r"(b[1]));
}

// ============ pre-convert: permuted K / V^T -> bf16 hi/lo fragment layout ====
__global__ __launch_bounds__(256) void preconv_kernel(int /*dummy*/)
{
    __shared__ __nv_bfloat16 sVH[64][66];
    __shared__ __nv_bfloat16 sVL[64][66];
    int tile = blockIdx.x, h = blockIdx.y;
    int tid = threadIdx.x;
    int keyl = tid >> 2, grp = tid & 3;
    int kidx = tile * 64 + keyl;
    bool ok = kidx < N_TOK;
    int src = ok ? g_perm[kidx] : 0;
    const float* kr = g_qkv + (size_t)src * (3 * CDIM) + CDIM + h * DH + grp * 16;
    const float* vr = kr + CDIM;

    float kb[16], vb[16];
#pragma unroll
    for (int j = 0; j < 4; j++) {
        float4 kv = ok ? *(const float4*)(kr + j * 4) : make_float4(0.f, 0.f, 0.f, 0.f);
        float4 vv = ok ? *(const float4*)(vr + j * 4) : make_float4(0.f, 0.f, 0.f, 0.f);
        kb[j * 4 + 0] = kv.x; kb[j * 4 + 1] = kv.y; kb[j * 4 + 2] = kv.z; kb[j * 4 + 3] = kv.w;
        vb[j * 4 + 0] = vv.x; vb[j * 4 + 1] = vv.y; vb[j * 4 + 2] = vv.z; vb[j * 4 + 3] = vv.w;
    }
    uint32_t* kout = &g_kc[h][kidx][grp * 16];
#pragma unroll
    for (int pj = 0; pj < 8; pj++) {
        float a = kb[2 * pj], b = kb[2 * pj + 1];
        float ha = bf16rt(a), hb = bf16rt(b);
        int sh = 4 * (pj & 3) + (pj >> 2);
        kout[sh] = pack2(ha, hb);
        kout[sh + 2] = pack2(a - ha, b - hb);
    }
#pragma unroll
    for (int d = 0; d < 16; d++) {
        float v = vb[d];
        float hv = bf16rt(v);
        sVH[grp * 16 + d][keyl] = __float2bfloat16(v);
        sVL[grp * 16 + d][keyl] = __float2bfloat16(v - hv);
    }
    __syncthreads();
    int dim = tid >> 2, grp2 = tid & 3;
    uint32_t* vout = &g_vtc[h][dim][tile * 64 + grp2 * 16];
#pragma unroll
    for (int pj = 0; pj < 8; pj++) {
        int k0 = grp2 * 16 + 2 * pj;
        uint32_t hi = ((uint32_t)__bfloat16_as_ushort(sVH[dim][k0 + 1]) << 16)
                    | __bfloat16_as_ushort(sVH[dim][k0]);
        uint32_t lo = ((uint32_t)__bfloat16_as_ushort(sVL[dim][k0 + 1]) << 16)
                    | __bfloat16_as_ushort(sVL[dim][k0]);
        int sh = 4 * (pj & 3) + (pj >> 2);
        vout[sh] = hi;
        vout[sh + 2] = lo;
    }
}

// ================== tensor-core flash attention (bf16x3, cp.async) ===========
// R8 configuration: 256-thread CTA, 64 query rows, 1 CTA/SM (proven optimum).
#define FS_STAGE_U32 8704           // K 64*68 + VT 64*68
#define FS_STAGE_BYTES (FS_STAGE_U32 * 4)
#define FS_RED_U32 (2 * FS_STAGE_U32)
#define FS_TOTAL_BYTES ((FS_RED_U32 + 448) * 4)

__device__ __forceinline__ void copy_tile(uint32_t dstb, int ti, int h, int tid)
{
    int row = tid >> 2, seg = tid & 3;
    uint32_t kd = dstb + (uint32_t)(row * 68 + seg * 16) * 4;
    const uint32_t* ksp = &g_kc[h][ti * 64 + row][seg * 16];
    uint32_t vd = dstb + (uint32_t)(4352 + row * 68 + seg * 16) * 4;
    const uint32_t* vsp = &g_vtc[h][row][ti * 64 + seg * 16];
#pragma unroll
    for (int c = 0; c < 4; c++) {
        asm volatile("cp.async.ca.shared.global [%0], [%1], 16;"
                     :: "r"(kd + c * 16), "l"(ksp + c * 4) : "memory");
        asm volatile("cp.async.ca.shared.global [%0], [%1], 16;"
                     :: "r"(vd + c * 16), "l"(vsp + c * 4) : "memory");
    }
}

#define PAIR_BAR(mi) asm volatile("bar.sync %0, 64;" :: "r"((mi) + 1) : "memory")

template <int GRP>
__device__ __forceinline__ void group_pass(
    float sacc[4][4], float o[8][4], const uint32_t* Vb,
    float* red0, float* red1, float* s_m, float* s_l, float* s_al,
    int base, int pend, int tid, int g, int t, int mi, int hf)
{
    int r0 = mi * 16 + g, r1 = r0 + 8;
    float pm0 = -1e30f, pm1 = -1e30f;
#pragma unroll
    for (int nj = 0; nj < 4; nj++) {
        int kc = base + (hf * 4 + nj) * 8 + 2 * t;
        bool in0 = (GRP == 0) ? (kc < pend)
                              : ((kc < REG_N) || (kc >= pend && kc < N_TOK));
        bool in1 = (GRP == 0) ? (kc + 1 < pend)
                              : ((kc + 1 < REG_N) || (kc + 1 >= pend && kc + 1 < N_TOK));
        if (in0) { pm0 = fmaxf(pm0, sacc[nj][0]); pm1 = fmaxf(pm1, sacc[nj][2]); }
        if (in1) { pm0 = fmaxf(pm0, sacc[nj][1]); pm1 = fmaxf(pm1, sacc[nj][3]); }
    }
    pm0 = fmaxf(pm0, __shfl_xor_sync(0xffffffffu, pm0, 1));
    pm0 = fmaxf(pm0, __shfl_xor_sync(0xffffffffu, pm0, 2));
    pm1 = fmaxf(pm1, __shfl_xor_sync(0xffffffffu, pm1, 1));
    pm1 = fmaxf(pm1, __shfl_xor_sync(0xffffffffu, pm1, 2));
    if (t == 0) {
        float* rd = hf ? red1 : red0;
        rd[r0] = pm0; rd[r1] = pm1;
    }
    PAIR_BAR(mi);
    if (hf == 0 && t == 0) {
#pragma unroll
        for (int rr = 0; rr < 2; rr++) {
            int r = rr ? r1 : r0;
            float mt = fmaxf(red0[r], red1[r]);
            float mo = s_m[r];
            float mn2 = fmaxf(mo, mt);
            s_al[r] = __expf(mo - mn2);
            s_m[r] = mn2;
        }
    }
    PAIR_BAR(mi);
    float m0 = s_m[r0], m1 = s_m[r1];
    float p[4][4];
    float ps0 = 0.f, ps1 = 0.f;
#pragma unroll
    for (int nj = 0; nj < 4; nj++) {
        int kc = base + (hf * 4 + nj) * 8 + 2 * t;
        bool in0 = (GRP == 0) ? (kc < pend)
                              : ((kc < REG_N) || (kc >= pend && kc < N_TOK));
        bool in1 = (GRP == 0) ? (kc + 1 < pend)
                              : ((kc + 1 < REG_N) || (kc + 1 >= pend && kc + 1 < N_TOK));
        p[nj][0] = in0 ? __expf(sacc[nj][0] - m0) : 0.f;
        p[nj][1] = in1 ? __expf(sacc[nj][1] - m0) : 0.f;
        p[nj][2] = in0 ? __expf(sacc[nj][2] - m1) : 0.f;
        p[nj][3] = in1 ? __expf(sacc[nj][3] - m1) : 0.f;
        ps0 += p[nj][0] + p[nj][1];
        ps1 += p[nj][2] + p[nj][3];
    }
    ps0 += __shfl_xor_sync(0xffffffffu, ps0, 1);
    ps0 += __shfl_xor_sync(0xffffffffu, ps0, 2);
    ps1 += __shfl_xor_sync(0xffffffffu, ps1, 1);
    ps1 += __shfl_xor_sync(0xffffffffu, ps1, 2);
    if (t == 0) {
        float* rd = hf ? red1 : red0;
        rd[r0] = ps0; rd[r1] = ps1;
    }
    PAIR_BAR(mi);
    if (hf == 0 && t == 0) {
        s_l[r0] = s_l[r0] * s_al[r0] + red0[r0] + red1[r0];
        s_l[r1] = s_l[r1] * s_al[r1] + red0[r1] + red1[r1];
    }
    PAIR_BAR(mi);
    float al0 = s_al[r0], al1 = s_al[r1];
#pragma unroll
    for (int nd = 0; nd < 8; nd++) {
        o[nd][0] *= al0; o[nd][1] *= al0;
        o[nd][2] *= al1; o[nd][3] *= al1;
    }
    uint32_t ah[2][4], alo[2][4];
#pragma unroll
    for (int ks = 0; ks < 2; ks++) {
        float h00 = bf16rt(p[2 * ks][0]),     h01 = bf16rt(p[2 * ks][1]);
        float h02 = bf16rt(p[2 * ks][2]),     h03 = bf16rt(p[2 * ks][3]);
        float h10 = bf16rt(p[2 * ks + 1][0]), h11 = bf16rt(p[2 * ks + 1][1]);
        float h12 = bf16rt(p[2 * ks + 1][2]), h13 = bf16rt(p[2 * ks + 1][3]);
        ah[ks][0] = pack2(h00, h01);
        ah[ks][1] = pack2(h02, h03);
        ah[ks][2] = pack2(h10, h11);
        ah[ks][3] = pack2(h12, h13);
        alo[ks][0] = pack2(p[2 * ks][0] - h00,     p[2 * ks][1] - h01);
        alo[ks][1] = pack2(p[2 * ks][2] - h02,     p[2 * ks][3] - h03);
        alo[ks][2] = pack2(p[2 * ks + 1][0] - h10, p[2 * ks + 1][1] - h11);
        alo[ks][3] = pack2(p[2 * ks + 1][2] - h12, p[2 * ks + 1][3] - h13);
    }
#pragma unroll
    for (int nd = 0; nd < 8; nd++) {
        int db = (nd * 8 + g) * 68;
#pragma unroll
        for (int ks = 0; ks < 2; ks++) {
            uint4 vv = *(const uint4*)&Vb[db + (2 * hf + ks) * 16 + 4 * t];
            uint32_t bh[2] = { vv.x, vv.y };
            uint32_t bl[2] = { vv.z, vv.w };
            mma16816(o[nd], ah[ks], bh);
            mma16816(o[nd], alo[ks], bh);
            mma16816(o[nd], ah[ks], bl);
        }
    }
}

__global__ void __launch_bounds__(256) flash_kernel(int /*dummy*/)
{
    extern __shared__ char smc[];
    uint32_t* su = (uint32_t*)smc;
    float* fred = (float*)smc + FS_RED_U32;
    float* red0 = fred;
    float* red1 = fred + 64;
    float* s_mp = fred + 128;
    float* s_lp = fred + 192;
    float* s_mn = fred + 256;
    float* s_ln = fred + 320;
    float* s_al = fred + 384;

    int tid = threadIdx.x;
    int warp = tid >> 5, lane = tid & 31;
    int g = lane >> 2, t = lane & 3;
    int mi = warp >> 1, hf = warp & 1;
    int h = blockIdx.y, qt = blockIdx.x;
    int qbase = qt * 64;
    int pend = REG_N + g_npos[0];
    uint32_t sbyte = smem_u32(smc);

    // Q fragments (hi/lo bf16), scaled
    uint32_t Qh[4][4], Ql[4][4];
    {
        int r0g = qbase + mi * 16 + g;
        int r1g = r0g + 8;
        bool ok0 = r0g < N_TOK, ok1 = r1g < N_TOK;
        const float* q0p = g_qkv + (size_t)r0g * (3 * CDIM) + h * DH;
        const float* q1p = g_qkv + (size_t)r1g * (3 * CDIM) + h * DH;
#pragma unroll
        for (int ks = 0; ks < 4; ks++) {
            int d0 = ks * 16 + 2 * t;
            float2 x0 = ok0 ? *(const float2*)(q0p + d0) : make_float2(0.f, 0.f);
            float2 x1 = ok1 ? *(const float2*)(q1p + d0) : make_float2(0.f, 0.f);
            float2 x2 = ok0 ? *(const float2*)(q0p + d0 + 8) : make_float2(0.f, 0.f);
            float2 x3 = ok1 ? *(const float2*)(q1p + d0 + 8) : make_float2(0.f, 0.f);
            x0.x *= SCALE; x0.y *= SCALE; x1.x *= SCALE; x1.y *= SCALE;
            x2.x *= SCALE; x2.y *= SCALE; x3.x *= SCALE; x3.y *= SCALE;
            float h0x = bf16rt(x0.x), h0y = bf16rt(x0.y);
            float h1x = bf16rt(x1.x), h1y = bf16rt(x1.y);
            float h2x = bf16rt(x2.x), h2y = bf16rt(x2.y);
            float h3x = bf16rt(x3.x), h3y = bf16rt(x3.y);
            Qh[ks][0] = pack2(h0x, h0y); Ql[ks][0] = pack2(x0.x - h0x, x0.y - h0y);
            Qh[ks][1] = pack2(h1x, h1y); Ql[ks][1] = pack2(x1.x - h1x, x1.y - h1y);
            Qh[ks][2] = pack2(h2x, h2y); Ql[ks][2] = pack2(x2.x - h2x, x2.y - h2y);
            Qh[ks][3] = pack2(h3x, h3y); Ql[ks][3] = pack2(x3.x - h3x, x3.y - h3y);
        }
    }
    if (tid < 64) {
        s_mp[tid] = -1e30f; s_lp[tid] = 0.f;
        s_mn[tid] = -1e30f; s_ln[tid] = 0.f;
    }
    float o[2][8][4];
#pragma unroll
    for (int gi = 0; gi < 2; gi++)
#pragma unroll
        for (int nd = 0; nd < 8; nd++)
#pragma unroll
            for (int e = 0; e < 4; e++) o[gi][nd][e] = 0.f;

    // preload tile 0
    copy_tile(sbyte, 0, h, tid);
    asm volatile("cp.async.commit_group;" ::: "memory");

    for (int ti = 0; ti < NTILE; ti++) {
        if (ti + 1 < NTILE) {
            copy_tile(sbyte + ((ti + 1) & 1) * FS_STAGE_BYTES, ti + 1, h, tid);
            asm volatile("cp.async.commit_group;" ::: "memory");
            asm volatile("cp.async.wait_group 1;" ::: "memory");
        } else {
            asm volatile("cp.async.wait_group 0;" ::: "memory");
        }
        __syncthreads();
        const uint32_t* Kb = su + (ti & 1) * FS_STAGE_U32;
        const uint32_t* Vb = Kb + 4352;
        int base = ti * 64;

        float sacc[4][4];
#pragma unroll
        for (int nj = 0; nj < 4; nj++)
#pragma unroll
            for (int e = 0; e < 4; e++) sacc[nj][e] = 0.f;
#pragma unroll
        for (int nj = 0; nj < 4; nj++) {
            int keyb = ((hf * 4 + nj) * 8 + g) * 68;
#pragma unroll
            for (int ks = 0; ks < 4; ks++) {
                uint4 kv = *(const uint4*)&Kb[keyb + ks * 16 + 4 * t];
                uint32_t bh[2] = { kv.x, kv.y };
                uint32_t bl[2] = { kv.z, kv.w };
                mma16816(sacc[nj], Qh[ks], bh);
                mma16816(sacc[nj], Ql[ks], bh);
                mma16816(sacc[nj], Qh[ks], bl);
            }
        }
        bool runPos = base < pend;
        bool runNeg = (base < REG_N) || (base + 64 > pend);
        if (runPos)
            group_pass<0>(sacc, o[0], Vb, red0, red1,
                          s_mp, s_lp, s_al, base, pend, tid, g, t, mi, hf);
        if (runNeg)
            group_pass<1>(sacc, o[1], Vb, red0, red1,
                          s_mn, s_ln, s_al, base, pend, tid, g, t, mi, hf);
        __syncthreads();
    }

    // ---- epilogue: combine warp halves, normalize, pos/neg select ----
    float* PB = (float*)smc;
    float* NB = PB + 64 * 72;
    int r0 = mi * 16 + g, r1 = r0 + 8;
    if (hf == 1) {
#pragma unroll
        for (int nd = 0; nd < 8; nd++) {
            int c = nd * 8 + 2 * t;
            *(float2*)&PB[r0 * 72 + c] = make_float2(o[0][nd][0], o[0][nd][1]);
            *(float2*)&PB[r1 * 72 + c] = make_float2(o[0][nd][2], o[0][nd][3]);
            *(float2*)&NB[r0 * 72 + c] = make_float2(o[1][nd][0], o[1][nd][1]);
            *(float2*)&NB[r1 * 72 + c] = make_float2(o[1][nd][2], o[1][nd][3]);
        }
    }
    __syncthreads();
    if (hf == 0) {
        int q0 = qbase + r0, q1 = qbase + r1;
        float invlp0 = 1.f / s_lp[r0], invlp1 = 1.f / s_lp[r1];
        float invln0 = 1.f / s_ln[r0], invln1 = 1.f / s_ln[r1];
        bool reg0 = q0 < REG_N, reg1 = q1 < REG_N;
        float fl0 = (q0 >= REG_N && q0 < N_TOK) ? (g_flag[q0 - REG_N] ? 1.f : 0.f) : 0.f;
        float fl1 = (q1 >= REG_N && q1 < N_TOK) ? (g_flag[q1 - REG_N] ? 1.f : 0.f) : 0.f;
#pragma unroll
        for (int nd = 0; nd < 8; nd++) {
            int c = nd * 8 + 2 * t;
            float2 pp0 = *(float2*)&PB[r0 * 72 + c];
            float2 pp1 = *(float2*)&PB[r1 * 72 + c];
            float2 nn0 = *(float2*)&NB[r0 * 72 + c];
            float2 nn1 = *(float2*)&NB[r1 * 72 + c];
            float opx = (o[0][nd][0] + pp0.x) * invlp0;
            float opy = (o[0][nd][1] + pp0.y) * invlp0;
            float onx = (o[1][nd][0] + nn0.x) * invln0;
            float ony = (o[1][nd][1] + nn0.y) * invln0;
            float vx, vy;
            if (reg0) { vx = 0.5f * (opx + onx); vy = 0.5f * (opy + ony); }
            else      { vx = fl0 ? opx : onx;    vy = fl0 ? opy : ony; }
            if (q0 < N_TOK)
                *(float2*)(g_attn + (size_t)q0 * CDIM + h * DH + c) = make_float2(vx, vy);
            float opx1 = (o[0][nd][2] + pp1.x) * invlp1;
            float opy1 = (o[0][nd][3] + pp1.y) * invlp1;
            float onx1 = (o[1][nd][2] + nn1.x) * invln1;
            float ony1 = (o[1][nd][3] + nn1.y) * invln1;
            float wx, wy;
            if (reg1) { wx = 0.5f * (opx1 + onx1); wy = 0.5f * (opy1 + ony1); }
            else      { wx = fl1 ? opx1 : onx1;    wy = fl1 ? opy1 : ony1; }
            if (q1 < N_TOK)
                *(float2*)(g_attn + (size_t)q1 * CDIM + h * DH + c) = make_float2(wx, wy);
        }
    }
}

// ---------------- launcher ----------------
extern "C" void kernel_launch(void* const* d_in, const int* in_sizes, int n_in,
                              void* d_out, int out_size)
{
    const float* x = nullptr; const float* ginfo = nullptr;
    const float* wqkv = nullptr; const float* wproj = nullptr;
    const float* bproj = nullptr;
    for (int i = 0; i < n_in; i++) {
        switch (in_sizes[i]) {
            case N_TOK * CDIM:      x = (const float*)d_in[i]; break;
            case 12 * 2 * CDIM:     ginfo = (const float*)d_in[i]; break;
            case CDIM * 3 * CDIM:   wqkv = (const float*)d_in[i]; break;
            case CDIM * CDIM:       wproj = (const float*)d_in[i]; break;
            case CDIM:              bproj = (const float*)d_in[i]; break;
        }
    }
    float* out = (float*)d_out;

    float* qkv;  cudaGetSymbolAddress((void**)&qkv,  g_qkv);
    float* attn; cudaGetSymbolAddress((void**)&attn, g_attn);

    cudaFuncSetAttribute(gemm_mma, cudaFuncAttributeMaxDynamicSharedMemorySize,
                         GEMM_SMEM_BYTES);
    cudaFuncSetAttribute(flash_kernel, cudaFuncAttributeMaxDynamicSharedMemorySize,
                         FS_TOTAL_BYTES);

    // [1] QKV GEMM (tf32 mma x3, cp.async raw double-buffer)
    gemm_mma<<<dim3(3 * CDIM / 128, (N_TOK + 127) / 128), 256, GEMM_SMEM_BYTES>>>(
        x, wqkv, nullptr, qkv, N_TOK, 3 * CDIM, CDIM);
    // [2] similarity
    sim_kernel<<<N_T, 128>>>(ginfo);
    // [3] minmax + mask + scan
    maskscan_kernel<<<1, 768>>>();
    // [4] pre-convert permuted K / V^T to bf16 hi/lo fragment layout
    preconv_kernel<<<dim3(NTILE, HEADS), 256>>>(0);
    // [5] flash attention (R8 config: 256 threads, cp.async double-buffered)
    flash_kernel<<<dim3(NTILE, HEADS), 256, FS_TOTAL_BYTES>>>(0);
    // [6] projection GEMM + bias (cp.async raw double-buffer)
    gemm_mma<<<dim3(CDIM / 128, (N_TOK + 127) / 128), 256, GEMM_SMEM_BYTES>>>(
        attn, wproj, bproj, out, N_TOK, CDIM, CDIM);
}

// round 12
// speedup vs baseline: 1.6499x; 1.0656x over previous
#include <cuda_runtime.h>
#include <cuda_bf16.h>
#include <math.h>
#include <stdint.h>

#define N_TOK 2309
#define N_T   2304
#define CDIM  1024
#define HEADS 16
#define DH    64
#define REG_N 5
#define SCALE 0.125f   // 64^-0.5
#define NTILE 37
#define KEYPAD (NTILE * 64)   // 2368

// ---------------- device scratch (static, no runtime alloc) ----------------
__device__ float g_qkv[(size_t)N_TOK * 3 * CDIM];
__device__ float g_attn[(size_t)N_TOK * CDIM];
__device__ float g_sim[N_T];
__device__ int   g_perm[N_TOK];
__device__ int   g_npos[1];
__device__ unsigned char g_flag[N_T];
// pre-converted bf16 hi/lo, permuted keys, fragment-ready layout
__device__ uint32_t g_kc [HEADS][KEYPAD][64];   // [head][key][slot]
__device__ uint32_t g_vtc[HEADS][DH][KEYPAD];   // [head][dim][tile*64+slot]

// ========== tf32x3 MMA GEMM, cp.async double-buffered raw-f32 smem ==========
#define SLAB 32
#define GA_PITCH 36
#define GB_PITCH 136
#define G_STAGEF (128 * GA_PITCH + SLAB * GB_PITCH)   // 8960 floats
#define G_STAGEB (G_STAGEF * 4)
#define G_BOFF  (128 * GA_PITCH)
#define GEMM_SMEM_BYTES (2 * G_STAGEB)                 // 71680

__device__ __forceinline__ float tf32r(float v)
{
    uint32_t u;
    asm("cvt.rna.tf32.f32 %0, %1;" : "=r"(u) : "f"(v));
    return __uint_as_float(u);
}

__device__ __forceinline__ void mma_tf32(float* d, const uint32_t* a, const uint32_t* b)
{
    asm volatile(
        "mma.sync.aligned.m16n8k8.row.col.f32.tf32.tf32.f32 "
        "{%0,%1,%2,%3}, {%4,%5,%6,%7}, {%8,%9}, {%0,%1,%2,%3};"
        : "+f"(d[0]), "+f"(d[1]), "+f"(d[2]), "+f"(d[3])
        : "r"(a[0]), "r"(a[1]), "r"(a[2]), "r"(a[3]), "r"(b[0]), "r"(b[1]));
}

__device__ __forceinline__ uint32_t smem_u32(const void* p)
{
    uint32_t a;
    asm("{ .reg .u64 t; cvta.to.shared.u64 t, %1; cvt.u32.u64 %0, t; }" : "=r"(a) : "l"(p));
    return a;
}

__global__ __launch_bounds__(256) void gemm_mma(
    const float* __restrict__ A, const float* __restrict__ B,
    const float* __restrict__ bias, float* __restrict__ C,
    int M, int N, int K)
{
    extern __shared__ float sm[];
    uint32_t sbyte = smem_u32(sm);

    int tid = threadIdx.x;
    int warp = tid >> 5, lane = tid & 31;
    int g = lane >> 2, t = lane & 3;
    int mw = (warp >> 1) * 32;
    int nw = (warp & 1) * 64;
    int brow = blockIdx.y, bcol = blockIdx.x;

    int aRow = tid >> 1;
    int aCol0 = (tid & 1) * 16;
    int aRowG = brow * 128 + aRow;
    bool aok = aRowG < M;
    const float* aptr = A + (size_t)aRowG * K + aCol0;
    uint32_t aDst = (uint32_t)(aRow * GA_PITCH + aCol0) * 4;
    int bRow = tid >> 3;
    int bCol0 = (tid & 7) * 16;
    const float* bptr = B + (size_t)bRow * N + bcol * 128 + bCol0;
    uint32_t bDst = (uint32_t)(G_BOFF + bRow * GB_PITCH + bCol0) * 4;

    float c[64];
#pragma unroll
    for (int i = 0; i < 64; i++) c[i] = 0.f;

    int nslab = K / SLAB;

    {
        uint32_t base = sbyte;
#pragma unroll
        for (int cch = 0; cch < 4; cch++) {
            if (aok) {
                asm volatile("cp.async.ca.shared.global [%0], [%1], 16;"
                             :: "r"(base + aDst + cch * 16), "l"(aptr + cch * 4) : "memory");
            } else {
                asm volatile("st.shared.v4.b32 [%0], {%1,%1,%1,%1};"
                             :: "r"(base + aDst + cch * 16), "r"(0) : "memory");
            }
            asm volatile("cp.async.ca.shared.global [%0], [%1], 16;"
                         :: "r"(base + bDst + cch * 16), "l"(bptr + cch * 4) : "memory");
        }
        asm volatile("cp.async.commit_group;" ::: "memory");
    }

    for (int s = 0; s < nslab; s++) {
        if (s + 1 < nslab) {
            uint32_t base = sbyte + ((s + 1) & 1) * G_STAGEB;
            const float* ap = aptr + (s + 1) * SLAB;
            const float* bp = bptr + (size_t)(s + 1) * SLAB * N;
#pragma unroll
            for (int cch = 0; cch < 4; cch++) {
                if (aok) {
                    asm volatile("cp.async.ca.shared.global [%0], [%1], 16;"
                                 :: "r"(base + aDst + cch * 16), "l"(ap + cch * 4) : "memory");
                } else {
                    asm volatile("st.shared.v4.b32 [%0], {%1,%1,%1,%1};"
                                 :: "r"(base + aDst + cch * 16), "r"(0) : "memory");
                }
                asm volatile("cp.async.ca.shared.global [%0], [%1], 16;"
                             :: "r"(base + bDst + cch * 16), "l"(bp + cch * 4) : "memory");
            }
            asm volatile("cp.async.commit_group;" ::: "memory");
            asm volatile("cp.async.wait_group 1;" ::: "memory");
        } else {
            asm volatile("cp.async.wait_group 0;" ::: "memory");
        }
        __syncthreads();

        const float* sA = sm + (s & 1) * G_STAGEF;
        const float* sB = sA + G_BOFF;

#pragma unroll
        for (int kk = 0; kk < SLAB; kk += 8) {
            uint32_t ah[2][4], al[2][4];
#pragma unroll
            for (int am = 0; am < 2; am++) {
#pragma unroll
                for (int rr = 0; rr < 4; rr++) {
                    int m = mw + am * 16 + g + ((rr & 1) << 3);
                    int k = kk + t + ((rr >> 1) << 2);
                    float v = sA[m * GA_PITCH + k];
                    float hi = tf32r(v);
                    ah[am][rr] = __float_as_uint(hi);
                    al[am][rr] = __float_as_uint(tf32r(v - hi));
                }
            }
#pragma unroll
            for (int an = 0; an < 8; an++) {
                int n = nw + an * 8 + g;
                uint32_t bh[2], bl[2];
#pragma unroll
                for (int rr = 0; rr < 2; rr++) {
                    int k = kk + t + rr * 4;
                    float v = sB[k * GB_PITCH + n];
                    float hi = tf32r(v);
                    bh[rr] = __float_as_uint(hi);
                    bl[rr] = __float_as_uint(tf32r(v - hi));
                }
#pragma unroll
                for (int am = 0; am < 2; am++) {
                    float* cc = &c[(am * 8 + an) * 4];
                    mma_tf32(cc, ah[am], bh);
                    mma_tf32(cc, al[am], bh);
                    mma_tf32(cc, ah[am], bl);
                }
            }
        }
        __syncthreads();
    }

#pragma unroll
    for (int am = 0; am < 2; am++) {
#pragma unroll
        for (int an = 0; an < 8; an++) {
            float* cc = &c[(am * 8 + an) * 4];
            int row0 = brow * 128 + mw + am * 16 + g;
            int col = bcol * 128 + nw + an * 8 + 2 * t;
            float bx = 0.f, by = 0.f;
            if (bias) { bx = bias[col]; by = bias[col + 1]; }
            if (row0 < M) {
                float2 o; o.x = cc[0] + bx; o.y = cc[1] + by;
                *(float2*)(C + (size_t)row0 * N + col) = o;
            }
            if (row0 + 8 < M) {
                float2 o; o.x = cc[2] + bx; o.y = cc[3] + by;
                *(float2*)(C + (size_t)(row0 + 8) * N + col) = o;
            }
        }
    }
}

// ---------------- similarity ----------------
__global__ void sim_kernel(const float* __restrict__ g_info)
{
    int t = blockIdx.x;
    int lane = threadIdx.x & 31, warp = threadIdx.x >> 5;
    __shared__ float wacc[4];
    const float* qrow = g_qkv + (size_t)(t + REG_N) * (3 * CDIM);
    float local = 0.f;
    for (int h = warp; h < HEADS; h += 4) {
        float q0 = qrow[h * DH + lane];
        float q1 = qrow[h * DH + lane + 32];
        float g0 = g_info[h * DH + lane];
        float g1 = g_info[h * DH + lane + 32];
        float d = q0 * g0 + q1 * g1;
        float nq = q0 * q0 + q1 * q1;
        float ng = g0 * g0 + g1 * g1;
#pragma unroll
        for (int o = 16; o > 0; o >>= 1) {
            d  += __shfl_xor_sync(0xffffffffu, d, o);
            nq += __shfl_xor_sync(0xffffffffu, nq, o);
            ng += __shfl_xor_sync(0xffffffffu, ng, o);
        }
        if (lane == 0) local += d / (sqrtf(nq) * sqrtf(ng));
    }
    if (lane == 0) wacc[warp] = local;
    __syncthreads();
    if (threadIdx.x == 0)
        g_sim[t] = (wacc[0] + wacc[1] + wacc[2] + wacc[3]) * (1.0f / 16.0f);
}

// ---------------- minmax + threshold + scan -> key permutation --------------
__global__ void maskscan_kernel()
{
    int tid = threadIdx.x;
    int lane = tid & 31, warp = tid >> 5;
    int t0 = tid * 3;
    float v0 = g_sim[t0], v1 = g_sim[t0 + 1], v2 = g_sim[t0 + 2];
    float mn = fminf(v0, fminf(v1, v2));
    float mx = fmaxf(v0, fmaxf(v1, v2));
#pragma unroll
    for (int o = 16; o > 0; o >>= 1) {
        mn = fminf(mn, __shfl_xor_sync(0xffffffffu, mn, o));
        mx = fmaxf(mx, __shfl_xor_sync(0xffffffffu, mx, o));
    }
    __shared__ float smn[24], smx[24];
    __shared__ float s_bmn, s_bmx;
    if (lane == 0) { smn[warp] = mn; smx[warp] = mx; }
    __syncthreads();
    if (tid == 0) {
        float a = smn[0], b = smx[0];
        for (int w = 1; w < 24; w++) { a = fminf(a, smn[w]); b = fmaxf(b, smx[w]); }
        s_bmn = a; s_bmx = b;
    }
    __syncthreads();
    float bmn = s_bmn;
    float inv = 1.0f / (s_bmx - bmn);
    int f[3]; int c = 0;
    f[0] = ((v0 - bmn) * inv > 0.9f) ? 1 : 0;
    f[1] = ((v1 - bmn) * inv > 0.9f) ? 1 : 0;
    f[2] = ((v2 - bmn) * inv > 0.9f) ? 1 : 0;
#pragma unroll
    for (int e = 0; e < 3; e++) {
        c += f[e];
        g_flag[t0 + e] = (unsigned char)f[e];
    }
    int incl = c;
#pragma unroll
    for (int o = 1; o < 32; o <<= 1) {
        int v = __shfl_up_sync(0xffffffffu, incl, o);
        if (lane >= o) incl += v;
    }
    __shared__ int wsum[24];
    __shared__ int s_npos;
    if (lane == 31) wsum[warp] = incl;
    __syncthreads();
    if (tid == 0) {
        int acc = 0;
        for (int w = 0; w < 24; w++) { int v = wsum[w]; wsum[w] = acc; acc += v; }
        s_npos = acc;
        g_npos[0] = acc;
        for (int i = 0; i < REG_N; i++) g_perm[i] = i;
    }
    __syncthreads();
    int excl = incl - c + wsum[warp];
    int npos = s_npos;
    int pp = excl;
#pragma unroll
    for (int e = 0; e < 3; e++) {
        int t = t0 + e;
        if (f[e]) { g_perm[REG_N + pp] = t + REG_N; pp++; }
        else      { g_perm[REG_N + npos + (t - pp)] = t + REG_N; }
    }
}

// ================== helpers ==================
__device__ __forceinline__ float bf16rt(float x)
{
    __nv_bfloat16 h = __float2bfloat16(x);
    return __bfloat162float(h);
}
__device__ __forceinline__ uint32_t pack2(float lo, float hi)
{
    uint32_t r;
    asm("cvt.rn.bf16x2.f32 %0, %1, %2;" : "=r"(r) : "f"(hi), "f"(lo));
    return r;
}
__device__ __forceinline__ void mma16816(float* d, const uint32_t* a, const uint32_t* b)
{
    asm volatile(
        "mma.sync.aligned.m16n8k16.row.col.f32.bf16.bf16.f32 "
        "{%0,%1,%2,%3},{%4,%5,%6,%7},{%8,%9},{%0,%1,%2,%3};"
        : "+f"(d[0]), "+f"(d[1]), "+f"(d[2]), "+f"(d[3])
        : "r"(a[0]), "r"(a[1]), "r"(a[2]), "r"(a[3]), "r"(b[0]), "r"(b[1]));
}

// ============ pre-convert: permuted K / V^T -> bf16 hi/lo fragment layout ====
__global__ __launch_bounds__(256) void preconv_kernel(int /*dummy*/)
{
    __shared__ __nv_bfloat16 sVH[64][66];
    __shared__ __nv_bfloat16 sVL[64][66];
    int tile = blockIdx.x, h = blockIdx.y;
    int tid = threadIdx.x;
    int keyl = tid >> 2, grp = tid & 3;
    int kidx = tile * 64 + keyl;
    bool ok = kidx < N_TOK;
    int src = ok ? g_perm[kidx] : 0;
    const float* kr = g_qkv + (size_t)src * (3 * CDIM) + CDIM + h * DH + grp * 16;
    const float* vr = kr + CDIM;

    float kb[16], vb[16];
#pragma unroll
    for (int j = 0; j < 4; j++) {
        float4 kv = ok ? *(const float4*)(kr + j * 4) : make_float4(0.f, 0.f, 0.f, 0.f);
        float4 vv = ok ? *(const float4*)(vr + j * 4) : make_float4(0.f, 0.f, 0.f, 0.f);
        kb[j * 4 + 0] = kv.x; kb[j * 4 + 1] = kv.y; kb[j * 4 + 2] = kv.z; kb[j * 4 + 3] = kv.w;
        vb[j * 4 + 0] = vv.x; vb[j * 4 + 1] = vv.y; vb[j * 4 + 2] = vv.z; vb[j * 4 + 3] = vv.w;
    }
    uint32_t* kout = &g_kc[h][kidx][grp * 16];
#pragma unroll
    for (int pj = 0; pj < 8; pj++) {
        float a = kb[2 * pj], b = kb[2 * pj + 1];
        float ha = bf16rt(a), hb = bf16rt(b);
        int sh = 4 * (pj & 3) + (pj >> 2);
        kout[sh] = pack2(ha, hb);
        kout[sh + 2] = pack2(a - ha, b - hb);
    }
#pragma unroll
    for (int d = 0; d < 16; d++) {
        float v = vb[d];
        float hv = bf16rt(v);
        sVH[grp * 16 + d][keyl] = __float2bfloat16(v);
        sVL[grp * 16 + d][keyl] = __float2bfloat16(v - hv);
    }
    __syncthreads();
    int dim = tid >> 2, grp2 = tid & 3;
    uint32_t* vout = &g_vtc[h][dim][tile * 64 + grp2 * 16];
#pragma unroll
    for (int pj = 0; pj < 8; pj++) {
        int k0 = grp2 * 16 + 2 * pj;
        uint32_t hi = ((uint32_t)__bfloat16_as_ushort(sVH[dim][k0 + 1]) << 16)
                    | __bfloat16_as_ushort(sVH[dim][k0]);
        uint32_t lo = ((uint32_t)__bfloat16_as_ushort(sVL[dim][k0 + 1]) << 16)
                    | __bfloat16_as_ushort(sVL[dim][k0]);
        int sh = 4 * (pj & 3) + (pj >> 2);
        vout[sh] = hi;
        vout[sh + 2] = lo;
    }
}

// ========== tensor-core flash attention: warp-owns-row, barrier-free ========
// 128-thread CTA, 4 warps, each warp: 16 query rows x ALL 64 keys.
// Softmax state in registers; quad-shfl reductions only; no intra-tile barriers.
#define FS_STAGE_U32 8704           // K 64*68 + VT 64*68
#define FS_STAGE_BYTES (FS_STAGE_U32 * 4)
#define FS_TOTAL_BYTES (2 * FS_STAGE_BYTES)   // 69632

__device__ __forceinline__ void copy_tile(uint32_t dstb, int ti, int h, int tid)
{
    int row = tid >> 1, s2 = (tid & 1) * 2;   // two 16-u32 segments per thread
    uint32_t kd = dstb + (uint32_t)(row * 68 + s2 * 16) * 4;
    const uint32_t* ksp = &g_kc[h][ti * 64 + row][s2 * 16];
    uint32_t vd = dstb + (uint32_t)(4352 + row * 68 + s2 * 16) * 4;
    const uint32_t* vsp = &g_vtc[h][row][ti * 64 + s2 * 16];
#pragma unroll
    for (int c = 0; c < 8; c++) {
        asm volatile("cp.async.ca.shared.global [%0], [%1], 16;"
                     :: "r"(kd + c * 16), "l"(ksp + c * 4) : "memory");
        asm volatile("cp.async.ca.shared.global [%0], [%1], 16;"
                     :: "r"(vd + c * 16), "l"(vsp + c * 4) : "memory");
    }
}

template <int GRP>
__device__ __forceinline__ void group_pass(
    const float sacc[8][4], float o[8][4], const uint32_t* Vb,
    float& m0, float& l0, float& m1, float& l1,
    int base, int pend, int g, int t)
{
    // masks + tile max (register/shfl only)
    float pm0 = -1e30f, pm1 = -1e30f;
#pragma unroll
    for (int nj = 0; nj < 8; nj++) {
        int kc = base + nj * 8 + 2 * t;
        bool in0 = (GRP == 0) ? (kc < pend)
                              : ((kc < REG_N) || (kc >= pend && kc < N_TOK));
        bool in1 = (GRP == 0) ? (kc + 1 < pend)
                              : ((kc + 1 < REG_N) || (kc + 1 >= pend && kc + 1 < N_TOK));
        if (in0) { pm0 = fmaxf(pm0, sacc[nj][0]); pm1 = fmaxf(pm1, sacc[nj][2]); }
        if (in1) { pm0 = fmaxf(pm0, sacc[nj][1]); pm1 = fmaxf(pm1, sacc[nj][3]); }
    }
    pm0 = fmaxf(pm0, __shfl_xor_sync(0xffffffffu, pm0, 1));
    pm0 = fmaxf(pm0, __shfl_xor_sync(0xffffffffu, pm0, 2));
    pm1 = fmaxf(pm1, __shfl_xor_sync(0xffffffffu, pm1, 1));
    pm1 = fmaxf(pm1, __shfl_xor_sync(0xffffffffu, pm1, 2));
    float mn0 = fmaxf(m0, pm0), mn1 = fmaxf(m1, pm1);
    float al0 = __expf(m0 - mn0), al1 = __expf(m1 - mn1);
    m0 = mn0; m1 = mn1;
    // exp + row sums
    float p[8][4];
    float ps0 = 0.f, ps1 = 0.f;
#pragma unroll
    for (int nj = 0; nj < 8; nj++) {
        int kc = base + nj * 8 + 2 * t;
        bool in0 = (GRP == 0) ? (kc < pend)
                              : ((kc < REG_N) || (kc >= pend && kc < N_TOK));
        bool in1 = (GRP == 0) ? (kc + 1 < pend)
                              : ((kc + 1 < REG_N) || (kc + 1 >= pend && kc + 1 < N_TOK));
        p[nj][0] = in0 ? __expf(sacc[nj][0] - mn0) : 0.f;
        p[nj][1] = in1 ? __expf(sacc[nj][1] - mn0) : 0.f;
        p[nj][2] = in0 ? __expf(sacc[nj][2] - mn1) : 0.f;
        p[nj][3] = in1 ? __expf(sacc[nj][3] - mn1) : 0.f;
        ps0 += p[nj][0] + p[nj][1];
        ps1 += p[nj][2] + p[nj][3];
    }
    ps0 += __shfl_xor_sync(0xffffffffu, ps0, 1);
    ps0 += __shfl_xor_sync(0xffffffffu, ps0, 2);
    ps1 += __shfl_xor_sync(0xffffffffu, ps1, 1);
    ps1 += __shfl_xor_sync(0xffffffffu, ps1, 2);
    l0 = l0 * al0 + ps0;
    l1 = l1 * al1 + ps1;
    // rescale accumulators
#pragma unroll
    for (int nd = 0; nd < 8; nd++) {
        o[nd][0] *= al0; o[nd][1] *= al0;
        o[nd][2] *= al1; o[nd][3] *= al1;
    }
    // pack P into A fragments (hi/lo bf16), 4 k-steps of 16 keys
    uint32_t ah[4][4], alo[4][4];
#pragma unroll
    for (int ks = 0; ks < 4; ks++) {
        float h00 = bf16rt(p[2 * ks][0]),     h01 = bf16rt(p[2 * ks][1]);
        float h02 = bf16rt(p[2 * ks][2]),     h03 = bf16rt(p[2 * ks][3]);
        float h10 = bf16rt(p[2 * ks + 1][0]), h11 = bf16rt(p[2 * ks + 1][1]);
        float h12 = bf16rt(p[2 * ks + 1][2]), h13 = bf16rt(p[2 * ks + 1][3]);
        ah[ks][0] = pack2(h00, h01);
        ah[ks][1] = pack2(h02, h03);
        ah[ks][2] = pack2(h10, h11);
        ah[ks][3] = pack2(h12, h13);
        alo[ks][0] = pack2(p[2 * ks][0] - h00,     p[2 * ks][1] - h01);
        alo[ks][1] = pack2(p[2 * ks][2] - h02,     p[2 * ks][3] - h03);
        alo[ks][2] = pack2(p[2 * ks + 1][0] - h10, p[2 * ks + 1][1] - h11);
        alo[ks][3] = pack2(p[2 * ks + 1][2] - h12, p[2 * ks + 1][3] - h13);
    }
    // PV over all 64 keys
#pragma unroll
    for (int nd = 0; nd < 8; nd++) {
        int db = (nd * 8 + g) * 68;
#pragma unroll
        for (int ks = 0; ks < 4; ks++) {
            uint4 vv = *(const uint4*)&Vb[db + ks * 16 + 4 * t];
            uint32_t bh[2] = { vv.x, vv.y };
            uint32_t bl[2] = { vv.z, vv.w };
            mma16816(o[nd], ah[ks], bh);
            mma16816(o[nd], alo[ks], bh);
            mma16816(o[nd], ah[ks], bl);
        }
    }
}

__global__ void __launch_bounds__(128) flash_kernel(int /*dummy*/)
{
    extern __shared__ char smc[];
    uint32_t* su = (uint32_t*)smc;

    int tid = threadIdx.x;
    int warp = tid >> 5, lane = tid & 31;
    int g = lane >> 2, t = lane & 3;
    int mi = warp;                     // 0..3, 16 rows each
    int h = blockIdx.y, qt = blockIdx.x;
    int qbase = qt * 64;
    int pend = REG_N + g_npos[0];
    uint32_t sbyte = smem_u32(smc);

    // Q fragments (hi/lo bf16), scaled
    uint32_t Qh[4][4], Ql[4][4];
    {
        int r0g = qbase + mi * 16 + g;
        int r1g = r0g + 8;
        bool ok0 = r0g < N_TOK, ok1 = r1g < N_TOK;
        const float* q0p = g_qkv + (size_t)r0g * (3 * CDIM) + h * DH;
        const float* q1p = g_qkv + (size_t)r1g * (3 * CDIM) + h * DH;
#pragma unroll
        for (int ks = 0; ks < 4; ks++) {
            int d0 = ks * 16 + 2 * t;
            float2 x0 = ok0 ? *(const float2*)(q0p + d0) : make_float2(0.f, 0.f);
            float2 x1 = ok1 ? *(const float2*)(q1p + d0) : make_float2(0.f, 0.f);
            float2 x2 = ok0 ? *(const float2*)(q0p + d0 + 8) : make_float2(0.f, 0.f);
            float2 x3 = ok1 ? *(const float2*)(q1p + d0 + 8) : make_float2(0.f, 0.f);
            x0.x *= SCALE; x0.y *= SCALE; x1.x *= SCALE; x1.y *= SCALE;
            x2.x *= SCALE; x2.y *= SCALE; x3.x *= SCALE; x3.y *= SCALE;
            float h0x = bf16rt(x0.x), h0y = bf16rt(x0.y);
            float h1x = bf16rt(x1.x), h1y = bf16rt(x1.y);
            float h2x = bf16rt(x2.x), h2y = bf16rt(x2.y);
            float h3x = bf16rt(x3.x), h3y = bf16rt(x3.y);
            Qh[ks][0] = pack2(h0x, h0y); Ql[ks][0] = pack2(x0.x - h0x, x0.y - h0y);
            Qh[ks][1] = pack2(h1x, h1y); Ql[ks][1] = pack2(x1.x - h1x, x1.y - h1y);
            Qh[ks][2] = pack2(h2x, h2y); Ql[ks][2] = pack2(x2.x - h2x, x2.y - h2y);
            Qh[ks][3] = pack2(h3x, h3y); Ql[ks][3] = pack2(x3.x - h3x, x3.y - h3y);
        }
    }

    // register softmax state: [pos, neg] x [row0, row1]
    float m_p0 = -1e30f, l_p0 = 0.f, m_p1 = -1e30f, l_p1 = 0.f;
    float m_n0 = -1e30f, l_n0 = 0.f, m_n1 = -1e30f, l_n1 = 0.f;
    float o[2][8][4];
#pragma unroll
    for (int gi = 0; gi < 2; gi++)
#pragma unroll
        for (int nd = 0; nd < 8; nd++)
#pragma unroll
            for (int e = 0; e < 4; e++) o[gi][nd][e] = 0.f;

    // preload tile 0
    copy_tile(sbyte, 0, h, tid);
    asm volatile("cp.async.commit_group;" ::: "memory");

    for (int ti = 0; ti < NTILE; ti++) {
        if (ti + 1 < NTILE) {
            copy_tile(sbyte + ((ti + 1) & 1) * FS_STAGE_BYTES, ti + 1, h, tid);
            asm volatile("cp.async.commit_group;" ::: "memory");
            asm volatile("cp.async.wait_group 1;" ::: "memory");
        } else {
            asm volatile("cp.async.wait_group 0;" ::: "memory");
        }
        __syncthreads();
        const uint32_t* Kb = su + (ti & 1) * FS_STAGE_U32;
        const uint32_t* Vb = Kb + 4352;
        int base = ti * 64;

        // S = Q @ K^T over all 64 keys (bf16x3)
        float sacc[8][4];
#pragma unroll
        for (int nj = 0; nj < 8; nj++)
#pragma unroll
            for (int e = 0; e < 4; e++) sacc[nj][e] = 0.f;
#pragma unroll
        for (int nj = 0; nj < 8; nj++) {
            int keyb = (nj * 8 + g) * 68;
#pragma unroll
            for (int ks = 0; ks < 4; ks++) {
                uint4 kv = *(const uint4*)&Kb[keyb + ks * 16 + 4 * t];
                uint32_t bh[2] = { kv.x, kv.y };
                uint32_t bl[2] = { kv.z, kv.w };
                mma16816(sacc[nj], Qh[ks], bh);
                mma16816(sacc[nj], Ql[ks], bh);
                mma16816(sacc[nj], Qh[ks], bl);
            }
        }
        bool runPos = base < pend;
        bool runNeg = (base < REG_N) || (base + 64 > pend);
        if (runPos)
            group_pass<0>(sacc, o[0], Vb, m_p0, l_p0, m_p1, l_p1, base, pend, g, t);
        if (runNeg)
            group_pass<1>(sacc, o[1], Vb, m_n0, l_n0, m_n1, l_n1, base, pend, g, t);
        __syncthreads();
    }

    // ---- epilogue: direct from registers ----
    int r0 = mi * 16 + g, r1 = r0 + 8;
    int q0 = qbase + r0, q1 = qbase + r1;
    float invlp0 = 1.f / l_p0, invlp1 = 1.f / l_p1;
    float invln0 = 1.f / l_n0, invln1 = 1.f / l_n1;
    bool reg0 = q0 < REG_N, reg1 = q1 < REG_N;
    float fl0 = (q0 >= REG_N && q0 < N_TOK) ? (g_flag[q0 - REG_N] ? 1.f : 0.f) : 0.f;
    float fl1 = (q1 >= REG_N && q1 < N_TOK) ? (g_flag[q1 - REG_N] ? 1.f : 0.f) : 0.f;
#pragma unroll
    for (int nd = 0; nd < 8; nd++) {
        int c = nd * 8 + 2 * t;
        float opx = o[0][nd][0] * invlp0;
        float opy = o[0][nd][1] * invlp0;
        float onx = o[1][nd][0] * invln0;
        float ony = o[1][nd][1] * invln0;
        float vx, vy;
        if (reg0) { vx = 0.5f * (opx + onx); vy = 0.5f * (opy + ony); }
        else      { vx = fl0 ? opx : onx;    vy = fl0 ? opy : ony; }
        if (q0 < N_TOK)
            *(float2*)(g_attn + (size_t)q0 * CDIM + h * DH + c) = make_float2(vx, vy);
        float opx1 = o[0][nd][2] * invlp1;
        float opy1 = o[0][nd][3] * invlp1;
        float onx1 = o[1][nd][2] * invln1;
        float ony1 = o[1][nd][3] * invln1;
        float wx, wy;
        if (reg1) { wx = 0.5f * (opx1 + onx1); wy = 0.5f * (opy1 + ony1); }
        else      { wx = fl1 ? opx1 : onx1;    wy = fl1 ? opy1 : ony1; }
        if (q1 < N_TOK)
            *(float2*)(g_attn + (size_t)q1 * CDIM + h * DH + c) = make_float2(wx, wy);
    }
}

// ---------------- launcher ----------------
extern "C" void kernel_launch(void* const* d_in, const int* in_sizes, int n_in,
                              void* d_out, int out_size)
{
    const float* x = nullptr; const float* ginfo = nullptr;
    const float* wqkv = nullptr; const float* wproj = nullptr;
    const float* bproj = nullptr;
    for (int i = 0; i < n_in; i++) {
        switch (in_sizes[i]) {
            case N_TOK * CDIM:      x = (const float*)d_in[i]; break;
            case 12 * 2 * CDIM:     ginfo = (const float*)d_in[i]; break;
            case CDIM * 3 * CDIM:   wqkv = (const float*)d_in[i]; break;
            case CDIM * CDIM:       wproj = (const float*)d_in[i]; break;
            case CDIM:              bproj = (const float*)d_in[i]; break;
        }
    }
    float* out = (float*)d_out;

    float* qkv;  cudaGetSymbolAddress((void**)&qkv,  g_qkv);
    float* attn; cudaGetSymbolAddress((void**)&attn, g_attn);

    cudaFuncSetAttribute(gemm_mma, cudaFuncAttributeMaxDynamicSharedMemorySize,
                         GEMM_SMEM_BYTES);
    cudaFuncSetAttribute(flash_kernel, cudaFuncAttributeMaxDynamicSharedMemorySize,
                         FS_TOTAL_BYTES);

    // [1] QKV GEMM (tf32 mma x3, cp.async raw double-buffer)
    gemm_mma<<<dim3(3 * CDIM / 128, (N_TOK + 127) / 128), 256, GEMM_SMEM_BYTES>>>(
        x, wqkv, nullptr, qkv, N_TOK, 3 * CDIM, CDIM);
    // [2] similarity
    sim_kernel<<<N_T, 128>>>(ginfo);
    // [3] minmax + mask + scan
    maskscan_kernel<<<1, 768>>>();
    // [4] pre-convert permuted K / V^T to bf16 hi/lo fragment layout
    preconv_kernel<<<dim3(NTILE, HEADS), 256>>>(0);
    // [5] flash attention (warp-owns-row, barrier-free softmax)
    flash_kernel<<<dim3(NTILE, HEADS), 128, FS_TOTAL_BYTES>>>(0);
    // [6] projection GEMM + bias (cp.async raw double-buffer)
    gemm_mma<<<dim3(CDIM / 128, (N_TOK + 127) / 128), 256, GEMM_SMEM_BYTES>>>(
        attn, wproj, bproj, out, N_TOK, CDIM, CDIM);
}

// round 14
// speedup vs baseline: 1.7406x; 1.0549x over previous
#include <cuda_runtime.h>
#include <cuda_bf16.h>
#include <math.h>
#include <stdint.h>

#define N_TOK 2309
#define N_T   2304
#define CDIM  1024
#define HEADS 16
#define DH    64
#define REG_N 5
#define SCALE 0.125f   // 64^-0.5
#define NTILE 37
#define KEYPAD (NTILE * 64)   // 2368

// ---------------- device scratch (static, no runtime alloc) ----------------
__device__ float g_qkv[(size_t)N_TOK * 3 * CDIM];
__device__ float g_attn[(size_t)N_TOK * CDIM];
__device__ float g_sim[N_T];
__device__ int   g_perm[N_TOK];
__device__ int   g_npos[1];
__device__ unsigned char g_flag[N_T];
// pre-converted bf16 hi/lo, permuted keys, fragment-ready layout
__device__ uint32_t g_kc [HEADS][KEYPAD][64];   // [head][key][slot]
__device__ uint32_t g_vtc[HEADS][DH][KEYPAD];   // [head][dim][tile*64+slot]

// ================= shared GEMM infrastructure =================
#define SLAB 32
#define GA_PITCH 36
#define GB_PITCH 136
#define G_STAGEF (128 * GA_PITCH + SLAB * GB_PITCH)   // 8960 floats
#define G_STAGEB (G_STAGEF * 4)
#define G_BOFF  (128 * GA_PITCH)
#define GEMM_SMEM_BYTES (2 * G_STAGEB)                 // 71680

__device__ __forceinline__ float tf32r(float v)
{
    uint32_t u;
    asm("cvt.rna.tf32.f32 %0, %1;" : "=r"(u) : "f"(v));
    return __uint_as_float(u);
}
__device__ __forceinline__ float bf16rt(float x)
{
    __nv_bfloat16 h = __float2bfloat16(x);
    return __bfloat162float(h);
}
__device__ __forceinline__ uint32_t pack2(float lo, float hi)
{
    uint32_t r;
    asm("cvt.rn.bf16x2.f32 %0, %1, %2;" : "=r"(r) : "f"(hi), "f"(lo));
    return r;
}
__device__ __forceinline__ void mma_tf32(float* d, const uint32_t* a, const uint32_t* b)
{
    asm volatile(
        "mma.sync.aligned.m16n8k8.row.col.f32.tf32.tf32.f32 "
        "{%0,%1,%2,%3}, {%4,%5,%6,%7}, {%8,%9}, {%0,%1,%2,%3};"
        : "+f"(d[0]), "+f"(d[1]), "+f"(d[2]), "+f"(d[3])
        : "r"(a[0]), "r"(a[1]), "r"(a[2]), "r"(a[3]), "r"(b[0]), "r"(b[1]));
}
__device__ __forceinline__ void mma16816(float* d, const uint32_t* a, const uint32_t* b)
{
    asm volatile(
        "mma.sync.aligned.m16n8k16.row.col.f32.bf16.bf16.f32 "
        "{%0,%1,%2,%3},{%4,%5,%6,%7},{%8,%9},{%0,%1,%2,%3};"
        : "+f"(d[0]), "+f"(d[1]), "+f"(d[2]), "+f"(d[3])
        : "r"(a[0]), "r"(a[1]), "r"(a[2]), "r"(a[3]), "r"(b[0]), "r"(b[1]));
}
__device__ __forceinline__ uint32_t smem_u32(const void* p)
{
    uint32_t a;
    asm("{ .reg .u64 t; cvta.to.shared.u64 t, %1; cvt.u32.u64 %0, t; }" : "=r"(a) : "l"(p));
    return a;
}

// copy helpers shared by both GEMM kernels (A: [128][36], B: [32][136] raw f32)
#define GEMM_COPY_SETUP() \
    int aRow = tid >> 1; \
    int aCol0 = (tid & 1) * 16; \
    int aRowG = brow * 128 + aRow; \
    bool aok = aRowG < M; \
    const float* aptr = A + (size_t)aRowG * K + aCol0; \
    uint32_t aDst = (uint32_t)(aRow * GA_PITCH + aCol0) * 4; \
    int bRow = tid >> 3; \
    int bCol0 = (tid & 7) * 16; \
    const float* bptr = B + (size_t)bRow * N + bcol * 128 + bCol0; \
    uint32_t bDst = (uint32_t)(G_BOFF + bRow * GB_PITCH + bCol0) * 4;

#define GEMM_COPY_SLAB(base_, ap_, bp_) \
    _Pragma("unroll") \
    for (int cch = 0; cch < 4; cch++) { \
        if (aok) { \
            asm volatile("cp.async.ca.shared.global [%0], [%1], 16;" \
                         :: "r"((base_) + aDst + cch * 16), "l"((ap_) + cch * 4) : "memory"); \
        } else { \
            asm volatile("st.shared.v4.b32 [%0], {%1,%1,%1,%1};" \
                         :: "r"((base_) + aDst + cch * 16), "r"(0) : "memory"); \
        } \
        asm volatile("cp.async.ca.shared.global [%0], [%1], 16;" \
                     :: "r"((base_) + bDst + cch * 16), "l"((bp_) + cch * 4) : "memory"); \
    } \
    asm volatile("cp.async.commit_group;" ::: "memory");

#define GEMM_EPILOGUE() \
    _Pragma("unroll") \
    for (int am = 0; am < 2; am++) { \
        _Pragma("unroll") \
        for (int an = 0; an < 8; an++) { \
            float* cc = &c[(am * 8 + an) * 4]; \
            int row0 = brow * 128 + mw + am * 16 + g; \
            int col = bcol * 128 + nw + an * 8 + 2 * t; \
            float bx = 0.f, by = 0.f; \
            if (bias) { bx = bias[col]; by = bias[col + 1]; } \
            if (row0 < M) { \
                float2 o; o.x = cc[0] + bx; o.y = cc[1] + by; \
                *(float2*)(C + (size_t)row0 * N + col) = o; \
            } \
            if (row0 + 8 < M) { \
                float2 o; o.x = cc[2] + bx; o.y = cc[3] + by; \
                *(float2*)(C + (size_t)(row0 + 8) * N + col) = o; \
            } \
        } \
    }

// ========== tf32x3 GEMM (precision-critical Q path) ==========
__global__ __launch_bounds__(256) void gemm_mma(
    const float* __restrict__ A, const float* __restrict__ B,
    const float* __restrict__ bias, float* __restrict__ C,
    int M, int N, int K)
{
    extern __shared__ float sm[];
    uint32_t sbyte = smem_u32(sm);

    int tid = threadIdx.x;
    int warp = tid >> 5, lane = tid & 31;
    int g = lane >> 2, t = lane & 3;
    int mw = (warp >> 1) * 32;
    int nw = (warp & 1) * 64;
    int brow = blockIdx.y, bcol = blockIdx.x;

    GEMM_COPY_SETUP();

    float c[64];
#pragma unroll
    for (int i = 0; i < 64; i++) c[i] = 0.f;

    int nslab = K / SLAB;
    { uint32_t base = sbyte; GEMM_COPY_SLAB(base, aptr, bptr); }

    for (int s = 0; s < nslab; s++) {
        if (s + 1 < nslab) {
            uint32_t base = sbyte + ((s + 1) & 1) * G_STAGEB;
            const float* ap = aptr + (s + 1) * SLAB;
            const float* bp = bptr + (size_t)(s + 1) * SLAB * N;
            GEMM_COPY_SLAB(base, ap, bp);
            asm volatile("cp.async.wait_group 1;" ::: "memory");
        } else {
            asm volatile("cp.async.wait_group 0;" ::: "memory");
        }
        __syncthreads();

        const float* sA = sm + (s & 1) * G_STAGEF;
        const float* sB = sA + G_BOFF;

#pragma unroll
        for (int kk = 0; kk < SLAB; kk += 8) {
            uint32_t ah[2][4], al[2][4];
#pragma unroll
            for (int am = 0; am < 2; am++) {
#pragma unroll
                for (int rr = 0; rr < 4; rr++) {
                    int m = mw + am * 16 + g + ((rr & 1) << 3);
                    int k = kk + t + ((rr >> 1) << 2);
                    float v = sA[m * GA_PITCH + k];
                    float hi = tf32r(v);
                    ah[am][rr] = __float_as_uint(hi);
                    al[am][rr] = __float_as_uint(tf32r(v - hi));
                }
            }
#pragma unroll
            for (int an = 0; an < 8; an++) {
                int n = nw + an * 8 + g;
                uint32_t bh[2], bl[2];
#pragma unroll
                for (int rr = 0; rr < 2; rr++) {
                    int k = kk + t + rr * 4;
                    float v = sB[k * GB_PITCH + n];
                    float hi = tf32r(v);
                    bh[rr] = __float_as_uint(hi);
                    bl[rr] = __float_as_uint(tf32r(v - hi));
                }
#pragma unroll
                for (int am = 0; am < 2; am++) {
                    float* cc = &c[(am * 8 + an) * 4];
                    mma_tf32(cc, ah[am], bh);
                    mma_tf32(cc, al[am], bh);
                    mma_tf32(cc, ah[am], bl);
                }
            }
        }
        __syncthreads();
    }
    GEMM_EPILOGUE();
}

// ========== bf16x3 GEMM (K/V columns + projection): half the HMMA count =====
__global__ __launch_bounds__(256) void gemm_bf16(
    const float* __restrict__ A, const float* __restrict__ B,
    const float* __restrict__ bias, float* __restrict__ C,
    int M, int N, int K)
{
    extern __shared__ float sm[];
    uint32_t sbyte = smem_u32(sm);

    int tid = threadIdx.x;
    int warp = tid >> 5, lane = tid & 31;
    int g = lane >> 2, t = lane & 3;
    int mw = (warp >> 1) * 32;
    int nw = (warp & 1) * 64;
    int brow = blockIdx.y, bcol = blockIdx.x;

    GEMM_COPY_SETUP();

    float c[64];
#pragma unroll
    for (int i = 0; i < 64; i++) c[i] = 0.f;

    int nslab = K / SLAB;
    { uint32_t base = sbyte; GEMM_COPY_SLAB(base, aptr, bptr); }

    for (int s = 0; s < nslab; s++) {
        if (s + 1 < nslab) {
            uint32_t base = sbyte + ((s + 1) & 1) * G_STAGEB;
            const float* ap = aptr + (s + 1) * SLAB;
            const float* bp = bptr + (size_t)(s + 1) * SLAB * N;
            GEMM_COPY_SLAB(base, ap, bp);
            asm volatile("cp.async.wait_group 1;" ::: "memory");
        } else {
            asm volatile("cp.async.wait_group 0;" ::: "memory");
        }
        __syncthreads();

        const float* sA = sm + (s & 1) * G_STAGEF;
        const float* sB = sA + G_BOFF;

#pragma unroll
        for (int kk = 0; kk < SLAB; kk += 16) {
            // A fragments: m16n8k16 layout (same convention as flash Q frags)
            uint32_t ah[2][4], al[2][4];
#pragma unroll
            for (int am = 0; am < 2; am++) {
                int m0 = mw + am * 16 + g;
                float2 p0 = *(const float2*)&sA[m0 * GA_PITCH + kk + 2 * t];
                float2 p1 = *(const float2*)&sA[(m0 + 8) * GA_PITCH + kk + 2 * t];
                float2 p2 = *(const float2*)&sA[m0 * GA_PITCH + kk + 8 + 2 * t];
                float2 p3 = *(const float2*)&sA[(m0 + 8) * GA_PITCH + kk + 8 + 2 * t];
                float h0x = bf16rt(p0.x), h0y = bf16rt(p0.y);
                float h1x = bf16rt(p1.x), h1y = bf16rt(p1.y);
                float h2x = bf16rt(p2.x), h2y = bf16rt(p2.y);
                float h3x = bf16rt(p3.x), h3y = bf16rt(p3.y);
                ah[am][0] = pack2(h0x, h0y); al[am][0] = pack2(p0.x - h0x, p0.y - h0y);
                ah[am][1] = pack2(h1x, h1y); al[am][1] = pack2(p1.x - h1x, p1.y - h1y);
                ah[am][2] = pack2(h2x, h2y); al[am][2] = pack2(p2.x - h2x, p2.y - h2y);
                ah[am][3] = pack2(h3x, h3y); al[am][3] = pack2(p3.x - h3x, p3.y - h3y);
            }
#pragma unroll
            for (int an = 0; an < 8; an++) {
                int n = nw + an * 8 + g;
                float b00 = sB[(kk + 2 * t) * GB_PITCH + n];
                float b01 = sB[(kk + 2 * t + 1) * GB_PITCH + n];
                float b10 = sB[(kk + 8 + 2 * t) * GB_PITCH + n];
                float b11 = sB[(kk + 8 + 2 * t + 1) * GB_PITCH + n];
                float hb00 = bf16rt(b00), hb01 = bf16rt(b01);
                float hb10 = bf16rt(b10), hb11 = bf16rt(b11);
                uint32_t bh[2], bl[2];
                bh[0] = pack2(hb00, hb01); bl[0] = pack2(b00 - hb00, b01 - hb01);
                bh[1] = pack2(hb10, hb11); bl[1] = pack2(b10 - hb10, b11 - hb11);
#pragma unroll
                for (int am = 0; am < 2; am++) {
                    float* cc = &c[(am * 8 + an) * 4];
                    mma16816(cc, ah[am], bh);
                    mma16816(cc, al[am], bh);
                    mma16816(cc, ah[am], bl);
                }
            }
        }
        __syncthreads();
    }
    GEMM_EPILOGUE();
}

// ---------------- similarity ----------------
__global__ void sim_kernel(const float* __restrict__ g_info)
{
    int t = blockIdx.x;
    int lane = threadIdx.x & 31, warp = threadIdx.x >> 5;
    __shared__ float wacc[4];
    const float* qrow = g_qkv + (size_t)(t + REG_N) * (3 * CDIM);
    float local = 0.f;
    for (int h = warp; h < HEADS; h += 4) {
        float q0 = qrow[h * DH + lane];
        float q1 = qrow[h * DH + lane + 32];
        float g0 = g_info[h * DH + lane];
        float g1 = g_info[h * DH + lane + 32];
        float d = q0 * g0 + q1 * g1;
        float nq = q0 * q0 + q1 * q1;
        float ng = g0 * g0 + g1 * g1;
#pragma unroll
        for (int o = 16; o > 0; o >>= 1) {
            d  += __shfl_xor_sync(0xffffffffu, d, o);
            nq += __shfl_xor_sync(0xffffffffu, nq, o);
            ng += __shfl_xor_sync(0xffffffffu, ng, o);
        }
        if (lane == 0) local += d / (sqrtf(nq) * sqrtf(ng));
    }
    if (lane == 0) wacc[warp] = local;
    __syncthreads();
    if (threadIdx.x == 0)
        g_sim[t] = (wacc[0] + wacc[1] + wacc[2] + wacc[3]) * (1.0f / 16.0f);
}

// ---------------- minmax + threshold + scan -> key permutation --------------
__global__ void maskscan_kernel()
{
    int tid = threadIdx.x;
    int lane = tid & 31, warp = tid >> 5;
    int t0 = tid * 3;
    float v0 = g_sim[t0], v1 = g_sim[t0 + 1], v2 = g_sim[t0 + 2];
    float mn = fminf(v0, fminf(v1, v2));
    float mx = fmaxf(v0, fmaxf(v1, v2));
#pragma unroll
    for (int o = 16; o > 0; o >>= 1) {
        mn = fminf(mn, __shfl_xor_sync(0xffffffffu, mn, o));
        mx = fmaxf(mx, __shfl_xor_sync(0xffffffffu, mx, o));
    }
    __shared__ float smn[24], smx[24];
    __shared__ float s_bmn, s_bmx;
    if (lane == 0) { smn[warp] = mn; smx[warp] = mx; }
    __syncthreads();
    if (tid == 0) {
        float a = smn[0], b = smx[0];
        for (int w = 1; w < 24; w++) { a = fminf(a, smn[w]); b = fmaxf(b, smx[w]); }
        s_bmn = a; s_bmx = b;
    }
    __syncthreads();
    float bmn = s_bmn;
    float inv = 1.0f / (s_bmx - bmn);
    int f[3]; int c = 0;
    f[0] = ((v0 - bmn) * inv > 0.9f) ? 1 : 0;
    f[1] = ((v1 - bmn) * inv > 0.9f) ? 1 : 0;
    f[2] = ((v2 - bmn) * inv > 0.9f) ? 1 : 0;
#pragma unroll
    for (int e = 0; e < 3; e++) {
        c += f[e];
        g_flag[t0 + e] = (unsigned char)f[e];
    }
    int incl = c;
#pragma unroll
    for (int o = 1; o < 32; o <<= 1) {
        int v = __shfl_up_sync(0xffffffffu, incl, o);
        if (lane >= o) incl += v;
    }
    __shared__ int wsum[24];
    __shared__ int s_npos;
    if (lane == 31) wsum[warp] = incl;
    __syncthreads();
    if (tid == 0) {
        int acc = 0;
        for (int w = 0; w < 24; w++) { int v = wsum[w]; wsum[w] = acc; acc += v; }
        s_npos = acc;
        g_npos[0] = acc;
        for (int i = 0; i < REG_N; i++) g_perm[i] = i;
    }
    __syncthreads();
    int excl = incl - c + wsum[warp];
    int npos = s_npos;
    int pp = excl;
#pragma unroll
    for (int e = 0; e < 3; e++) {
        int t = t0 + e;
        if (f[e]) { g_perm[REG_N + pp] = t + REG_N; pp++; }
        else      { g_perm[REG_N + npos + (t - pp)] = t + REG_N; }
    }
}

// ============ pre-convert: permuted K / V^T -> bf16 hi/lo fragment layout ====
__global__ __launch_bounds__(256) void preconv_kernel(int /*dummy*/)
{
    __shared__ __nv_bfloat16 sVH[64][66];
    __shared__ __nv_bfloat16 sVL[64][66];
    int tile = blockIdx.x, h = blockIdx.y;
    int tid = threadIdx.x;
    int keyl = tid >> 2, grp = tid & 3;
    int kidx = tile * 64 + keyl;
    bool ok = kidx < N_TOK;
    int src = ok ? g_perm[kidx] : 0;
    const float* kr = g_qkv + (size_t)src * (3 * CDIM) + CDIM + h * DH + grp * 16;
    const float* vr = kr + CDIM;

    float kb[16], vb[16];
#pragma unroll
    for (int j = 0; j < 4; j++) {
        float4 kv = ok ? *(const float4*)(kr + j * 4) : make_float4(0.f, 0.f, 0.f, 0.f);
        float4 vv = ok ? *(const float4*)(vr + j * 4) : make_float4(0.f, 0.f, 0.f, 0.f);
        kb[j * 4 + 0] = kv.x; kb[j * 4 + 1] = kv.y; kb[j * 4 + 2] = kv.z; kb[j * 4 + 3] = kv.w;
        vb[j * 4 + 0] = vv.x; vb[j * 4 + 1] = vv.y; vb[j * 4 + 2] = vv.z; vb[j * 4 + 3] = vv.w;
    }
    uint32_t* kout = &g_kc[h][kidx][grp * 16];
#pragma unroll
    for (int pj = 0; pj < 8; pj++) {
        float a = kb[2 * pj], b = kb[2 * pj + 1];
        float ha = bf16rt(a), hb = bf16rt(b);
        int sh = 4 * (pj & 3) + (pj >> 2);
        kout[sh] = pack2(ha, hb);
        kout[sh + 2] = pack2(a - ha, b - hb);
    }
#pragma unroll
    for (int d = 0; d < 16; d++) {
        float v = vb[d];
        float hv = bf16rt(v);
        sVH[grp * 16 + d][keyl] = __float2bfloat16(v);
        sVL[grp * 16 + d][keyl] = __float2bfloat16(v - hv);
    }
    __syncthreads();
    int dim = tid >> 2, grp2 = tid & 3;
    uint32_t* vout = &g_vtc[h][dim][tile * 64 + grp2 * 16];
#pragma unroll
    for (int pj = 0; pj < 8; pj++) {
        int k0 = grp2 * 16 + 2 * pj;
        uint32_t hi = ((uint32_t)__bfloat16_as_ushort(sVH[dim][k0 + 1]) << 16)
                    | __bfloat16_as_ushort(sVH[dim][k0]);
        uint32_t lo = ((uint32_t)__bfloat16_as_ushort(sVL[dim][k0 + 1]) << 16)
                    | __bfloat16_as_ushort(sVL[dim][k0]);
        int sh = 4 * (pj & 3) + (pj >> 2);
        vout[sh] = hi;
        vout[sh + 2] = lo;
    }
}

// ========== tensor-core flash attention: warp-owns-row, barrier-free ========
#define FS_STAGE_U32 8704           // K 64*68 + VT 64*68
#define FS_STAGE_BYTES (FS_STAGE_U32 * 4)
#define FS_TOTAL_BYTES (2 * FS_STAGE_BYTES)   // 69632

__device__ __forceinline__ void copy_tile(uint32_t dstb, int ti, int h, int tid)
{
    int row = tid >> 1, s2 = (tid & 1) * 2;
    uint32_t kd = dstb + (uint32_t)(row * 68 + s2 * 16) * 4;
    const uint32_t* ksp = &g_kc[h][ti * 64 + row][s2 * 16];
    uint32_t vd = dstb + (uint32_t)(4352 + row * 68 + s2 * 16) * 4;
    const uint32_t* vsp = &g_vtc[h][row][ti * 64 + s2 * 16];
#pragma unroll
    for (int c = 0; c < 8; c++) {
        asm volatile("cp.async.ca.shared.global [%0], [%1], 16;"
                     :: "r"(kd + c * 16), "l"(ksp + c * 4) : "memory");
        asm volatile("cp.async.ca.shared.global [%0], [%1], 16;"
                     :: "r"(vd + c * 16), "l"(vsp + c * 4) : "memory");
    }
}

template <int GRP>
__device__ __forceinline__ void group_pass(
    const float sacc[8][4], float o[8][4], const uint32_t* Vb,
    float& m0, float& l0, float& m1, float& l1,
    int base, int pend, int g, int t)
{
    float pm0 = -1e30f, pm1 = -1e30f;
#pragma unroll
    for (int nj = 0; nj < 8; nj++) {
        int kc = base + nj * 8 + 2 * t;
        bool in0 = (GRP == 0) ? (kc < pend)
                              : ((kc < REG_N) || (kc >= pend && kc < N_TOK));
        bool in1 = (GRP == 0) ? (kc + 1 < pend)
                              : ((kc + 1 < REG_N) || (kc + 1 >= pend && kc + 1 < N_TOK));
        if (in0) { pm0 = fmaxf(pm0, sacc[nj][0]); pm1 = fmaxf(pm1, sacc[nj][2]); }
        if (in1) { pm0 = fmaxf(pm0, sacc[nj][1]); pm1 = fmaxf(pm1, sacc[nj][3]); }
    }
    pm0 = fmaxf(pm0, __shfl_xor_sync(0xffffffffu, pm0, 1));
    pm0 = fmaxf(pm0, __shfl_xor_sync(0xffffffffu, pm0, 2));
    pm1 = fmaxf(pm1, __shfl_xor_sync(0xffffffffu, pm1, 1));
    pm1 = fmaxf(pm1, __shfl_xor_sync(0xffffffffu, pm1, 2));
    float mn0 = fmaxf(m0, pm0), mn1 = fmaxf(m1, pm1);
    float al0 = __expf(m0 - mn0), al1 = __expf(m1 - mn1);
    m0 = mn0; m1 = mn1;
    float p[8][4];
    float ps0 = 0.f, ps1 = 0.f;
#pragma unroll
    for (int nj = 0; nj < 8; nj++) {
        int kc = base + nj * 8 + 2 * t;
        bool in0 = (GRP == 0) ? (kc < pend)
                              : ((kc < REG_N) || (kc >= pend && kc < N_TOK));
        bool in1 = (GRP == 0) ? (kc + 1 < pend)
                              : ((kc + 1 < REG_N) || (kc + 1 >= pend && kc + 1 < N_TOK));
        p[nj][0] = in0 ? __expf(sacc[nj][0] - mn0) : 0.f;
        p[nj][1] = in1 ? __expf(sacc[nj][1] - mn0) : 0.f;
        p[nj][2] = in0 ? __expf(sacc[nj][2] - mn1) : 0.f;
        p[nj][3] = in1 ? __expf(sacc[nj][3] - mn1) : 0.f;
        ps0 += p[nj][0] + p[nj][1];
        ps1 += p[nj][2] + p[nj][3];
    }
    ps0 += __shfl_xor_sync(0xffffffffu, ps0, 1);
    ps0 += __shfl_xor_sync(0xffffffffu, ps0, 2);
    ps1 += __shfl_xor_sync(0xffffffffu, ps1, 1);
    ps1 += __shfl_xor_sync(0xffffffffu, ps1, 2);
    l0 = l0 * al0 + ps0;
    l1 = l1 * al1 + ps1;
#pragma unroll
    for (int nd = 0; nd < 8; nd++) {
        o[nd][0] *= al0; o[nd][1] *= al0;
        o[nd][2] *= al1; o[nd][3] *= al1;
    }
    uint32_t ah[4][4], alo[4][4];
#pragma unroll
    for (int ks = 0; ks < 4; ks++) {
        float h00 = bf16rt(p[2 * ks][0]),     h01 = bf16rt(p[2 * ks][1]);
        float h02 = bf16rt(p[2 * ks][2]),     h03 = bf16rt(p[2 * ks][3]);
        float h10 = bf16rt(p[2 * ks + 1][0]), h11 = bf16rt(p[2 * ks + 1][1]);
        float h12 = bf16rt(p[2 * ks + 1][2]), h13 = bf16rt(p[2 * ks + 1][3]);
        ah[ks][0] = pack2(h00, h01);
        ah[ks][1] = pack2(h02, h03);
        ah[ks][2] = pack2(h10, h11);
        ah[ks][3] = pack2(h12, h13);
        alo[ks][0] = pack2(p[2 * ks][0] - h00,     p[2 * ks][1] - h01);
        alo[ks][1] = pack2(p[2 * ks][2] - h02,     p[2 * ks][3] - h03);
        alo[ks][2] = pack2(p[2 * ks + 1][0] - h10, p[2 * ks + 1][1] - h11);
        alo[ks][3] = pack2(p[2 * ks + 1][2] - h12, p[2 * ks + 1][3] - h13);
    }
#pragma unroll
    for (int nd = 0; nd < 8; nd++) {
        int db = (nd * 8 + g) * 68;
#pragma unroll
        for (int ks = 0; ks < 4; ks++) {
            uint4 vv = *(const uint4*)&Vb[db + ks * 16 + 4 * t];
            uint32_t bh[2] = { vv.x, vv.y };
            uint32_t bl[2] = { vv.z, vv.w };
            mma16816(o[nd], ah[ks], bh);
            mma16816(o[nd], alo[ks], bh);
            mma16816(o[nd], ah[ks], bl);
        }
    }
}

__global__ void __launch_bounds__(128) flash_kernel(int /*dummy*/)
{
    extern __shared__ char smc[];
    uint32_t* su = (uint32_t*)smc;

    int tid = threadIdx.x;
    int warp = tid >> 5, lane = tid & 31;
    int g = lane >> 2, t = lane & 3;
    int mi = warp;
    int h = blockIdx.y, qt = blockIdx.x;
    int qbase = qt * 64;
    int pend = REG_N + g_npos[0];
    uint32_t sbyte = smem_u32(smc);

    uint32_t Qh[4][4], Ql[4][4];
    {
        int r0g = qbase + mi * 16 + g;
        int r1g = r0g + 8;
        bool ok0 = r0g < N_TOK, ok1 = r1g < N_TOK;
        const float* q0p = g_qkv + (size_t)r0g * (3 * CDIM) + h * DH;
        const float* q1p = g_qkv + (size_t)r1g * (3 * CDIM) + h * DH;
#pragma unroll
        for (int ks = 0; ks < 4; ks++) {
            int d0 = ks * 16 + 2 * t;
            float2 x0 = ok0 ? *(const float2*)(q0p + d0) : make_float2(0.f, 0.f);
            float2 x1 = ok1 ? *(const float2*)(q1p + d0) : make_float2(0.f, 0.f);
            float2 x2 = ok0 ? *(const float2*)(q0p + d0 + 8) : make_float2(0.f, 0.f);
            float2 x3 = ok1 ? *(const float2*)(q1p + d0 + 8) : make_float2(0.f, 0.f);
            x0.x *= SCALE; x0.y *= SCALE; x1.x *= SCALE; x1.y *= SCALE;
            x2.x *= SCALE; x2.y *= SCALE; x3.x *= SCALE; x3.y *= SCALE;
            float h0x = bf16rt(x0.x), h0y = bf16rt(x0.y);
            float h1x = bf16rt(x1.x), h1y = bf16rt(x1.y);
            float h2x = bf16rt(x2.x), h2y = bf16rt(x2.y);
            float h3x = bf16rt(x3.x), h3y = bf16rt(x3.y);
            Qh[ks][0] = pack2(h0x, h0y); Ql[ks][0] = pack2(x0.x - h0x, x0.y - h0y);
            Qh[ks][1] = pack2(h1x, h1y); Ql[ks][1] = pack2(x1.x - h1x, x1.y - h1y);
            Qh[ks][2] = pack2(h2x, h2y); Ql[ks][2] = pack2(x2.x - h2x, x2.y - h2y);
            Qh[ks][3] = pack2(h3x, h3y); Ql[ks][3] = pack2(x3.x - h3x, x3.y - h3y);
        }
    }

    float m_p0 = -1e30f, l_p0 = 0.f, m_p1 = -1e30f, l_p1 = 0.f;
    float m_n0 = -1e30f, l_n0 = 0.f, m_n1 = -1e30f, l_n1 = 0.f;
    float o[2][8][4];
#pragma unroll
    for (int gi = 0; gi < 2; gi++)
#pragma unroll
        for (int nd = 0; nd < 8; nd++)
#pragma unroll
            for (int e = 0; e < 4; e++) o[gi][nd][e] = 0.f;

    copy_tile(sbyte, 0, h, tid);
    asm volatile("cp.async.commit_group;" ::: "memory");

    for (int ti = 0; ti < NTILE; ti++) {
        if (ti + 1 < NTILE) {
            copy_tile(sbyte + ((ti + 1) & 1) * FS_STAGE_BYTES, ti + 1, h, tid);
            asm volatile("cp.async.commit_group;" ::: "memory");
            asm volatile("cp.async.wait_group 1;" ::: "memory");
        } else {
            asm volatile("cp.async.wait_group 0;" ::: "memory");
        }
        __syncthreads();
        const uint32_t* Kb = su + (ti & 1) * FS_STAGE_U32;
        const uint32_t* Vb = Kb + 4352;
        int base = ti * 64;

        float sacc[8][4];
#pragma unroll
        for (int nj = 0; nj < 8; nj++)
#pragma unroll
            for (int e = 0; e < 4; e++) sacc[nj][e] = 0.f;
#pragma unroll
        for (int nj = 0; nj < 8; nj++) {
            int keyb = (nj * 8 + g) * 68;
#pragma unroll
            for (int ks = 0; ks < 4; ks++) {
                uint4 kv = *(const uint4*)&Kb[keyb + ks * 16 + 4 * t];
                uint32_t bh[2] = { kv.x, kv.y };
                uint32_t bl[2] = { kv.z, kv.w };
                mma16816(sacc[nj], Qh[ks], bh);
                mma16816(sacc[nj], Ql[ks], bh);
                mma16816(sacc[nj], Qh[ks], bl);
            }
        }
        bool runPos = base < pend;
        bool runNeg = (base < REG_N) || (base + 64 > pend);
        if (runPos)
            group_pass<0>(sacc, o[0], Vb, m_p0, l_p0, m_p1, l_p1, base, pend, g, t);
        if (runNeg)
            group_pass<1>(sacc, o[1], Vb, m_n0, l_n0, m_n1, l_n1, base, pend, g, t);
        __syncthreads();
    }

    int r0 = mi * 16 + g, r1 = r0 + 8;
    int q0 = qbase + r0, q1 = qbase + r1;
    float invlp0 = 1.f / l_p0, invlp1 = 1.f / l_p1;
    float invln0 = 1.f / l_n0, invln1 = 1.f / l_n1;
    bool reg0 = q0 < REG_N, reg1 = q1 < REG_N;
    float fl0 = (q0 >= REG_N && q0 < N_TOK) ? (g_flag[q0 - REG_N] ? 1.f : 0.f) : 0.f;
    float fl1 = (q1 >= REG_N && q1 < N_TOK) ? (g_flag[q1 - REG_N] ? 1.f : 0.f) : 0.f;
#pragma unroll
    for (int nd = 0; nd < 8; nd++) {
        int c = nd * 8 + 2 * t;
        float opx = o[0][nd][0] * invlp0;
        float opy = o[0][nd][1] * invlp0;
        float onx = o[1][nd][0] * invln0;
        float ony = o[1][nd][1] * invln0;
        float vx, vy;
        if (reg0) { vx = 0.5f * (opx + onx); vy = 0.5f * (opy + ony); }
        else      { vx = fl0 ? opx : onx;    vy = fl0 ? opy : ony; }
        if (q0 < N_TOK)
            *(float2*)(g_attn + (size_t)q0 * CDIM + h * DH + c) = make_float2(vx, vy);
        float opx1 = o[0][nd][2] * invlp1;
        float opy1 = o[0][nd][3] * invlp1;
        float onx1 = o[1][nd][2] * invln1;
        float ony1 = o[1][nd][3] * invln1;
        float wx, wy;
        if (reg1) { wx = 0.5f * (opx1 + onx1); wy = 0.5f * (opy1 + ony1); }
        else      { wx = fl1 ? opx1 : onx1;    wy = fl1 ? opy1 : ony1; }
        if (q1 < N_TOK)
            *(float2*)(g_attn + (size_t)q1 * CDIM + h * DH + c) = make_float2(wx, wy);
    }
}

// ---------------- launcher ----------------
extern "C" void kernel_launch(void* const* d_in, const int* in_sizes, int n_in,
                              void* d_out, int out_size)
{
    const float* x = nullptr; const float* ginfo = nullptr;
    const float* wqkv = nullptr; const float* wproj = nullptr;
    const float* bproj = nullptr;
    for (int i = 0; i < n_in; i++) {
        switch (in_sizes[i]) {
            case N_TOK * CDIM:      x = (const float*)d_in[i]; break;
            case 12 * 2 * CDIM:     ginfo = (const float*)d_in[i]; break;
            case CDIM * 3 * CDIM:   wqkv = (const float*)d_in[i]; break;
            case CDIM * CDIM:       wproj = (const float*)d_in[i]; break;
            case CDIM:              bproj = (const float*)d_in[i]; break;
        }
    }
    float* out = (float*)d_out;

    float* qkv;  cudaGetSymbolAddress((void**)&qkv,  g_qkv);
    float* attn; cudaGetSymbolAddress((void**)&attn, g_attn);

    cudaFuncSetAttribute(gemm_mma, cudaFuncAttributeMaxDynamicSharedMemorySize,
                         GEMM_SMEM_BYTES);
    cudaFuncSetAttribute(gemm_bf16, cudaFuncAttributeMaxDynamicSharedMemorySize,
                         GEMM_SMEM_BYTES);
    cudaFuncSetAttribute(flash_kernel, cudaFuncAttributeMaxDynamicSharedMemorySize,
                         FS_TOTAL_BYTES);

    // [1] Q GEMM: columns 0..1023 (precision-critical), tf32x3
    gemm_mma<<<dim3(CDIM / 128, (N_TOK + 127) / 128), 256, GEMM_SMEM_BYTES>>>(
        x, wqkv, nullptr, qkv, N_TOK, 3 * CDIM, CDIM);
    // [2] KV GEMM: columns 1024..3071, bf16x3 (half the HMMA count)
    gemm_bf16<<<dim3(2 * CDIM / 128, (N_TOK + 127) / 128), 256, GEMM_SMEM_BYTES>>>(
        x, wqkv + CDIM, nullptr, qkv + CDIM, N_TOK, 3 * CDIM, CDIM);
    // [3] similarity
    sim_kernel<<<N_T, 128>>>(ginfo);
    // [4] minmax + mask + scan
    maskscan_kernel<<<1, 768>>>();
    // [5] pre-convert permuted K / V^T to bf16 hi/lo fragment layout
    preconv_kernel<<<dim3(NTILE, HEADS), 256>>>(0);
    // [6] flash attention (warp-owns-row, barrier-free softmax)
    flash_kernel<<<dim3(NTILE, HEADS), 128, FS_TOTAL_BYTES>>>(0);
    // [7] projection GEMM + bias, bf16x3
    gemm_bf16<<<dim3(CDIM / 128, (N_TOK + 127) / 128), 256, GEMM_SMEM_BYTES>>>(
        attn, wproj, bproj, out, N_TOK, CDIM, CDIM);
}